// round 13
// baseline (speedup 1.0000x reference)
#include <cuda_runtime.h>
#include <cuda_bf16.h>
#include <cuda_fp16.h>
#include <math.h>
#include <stdint.h>

#define NIMG 2
#define MALL 242991
#define MPOS 80997
#define MPROP 4741
#define POSTK 1000
#define NEG_INF (-1e9f)
#define NW 149
#define NSORT 8192
#define RSCALE 4096.0f
#define RINV   2.44140625e-4f   // 1/4096 exact

__constant__ int c_H[5]      = {200, 100, 50, 25, 13};
__constant__ int c_W[5]      = {304, 152, 76, 38, 19};
__constant__ int c_stride[5] = {4, 8, 16, 32, 64};
__constant__ int c_size[5]   = {32, 64, 128, 256, 512};
__constant__ int c_hw[5]     = {60800, 15200, 3800, 950, 247};
__constant__ int c_hwa[5]    = {182400, 45600, 11400, 2850, 741};
__constant__ int c_abase[5]  = {0, 182400, 228000, 239400, 242250};
__constant__ int c_pbase[5]  = {0, 60800, 76000, 79800, 80750};
__constant__ int c_k[5]      = {1000, 1000, 1000, 1000, 741};
__constant__ int c_sbase[5]  = {0, 1000, 2000, 3000, 4000};
__constant__ int c_tstart[6] = {0, 475, 594, 624, 632, 634};     // ceil(hw/128) cum
__constant__ int c_ft[6]     = {0, 950, 1188, 1248, 1263, 1267}; // ceil(hw/64) cum

// ---------------------------------------------------------------------------
// Device scratch
// ---------------------------------------------------------------------------
__device__ __half g_spA[2][(size_t)NIMG * MPOS * 256];  // [q][n*MPOS+pos][ci]  q=0:h q=1:r*4096
__device__ __half g_spB[2][256 * 2304];                 // [q][co][tap*256+ci]
__device__ float  g_t[(size_t)NIMG * MPOS * 256];
__device__ float  g_logits[NIMG * MALL];
__device__ float  g_deltas[(size_t)NIMG * MALL * 4];
__device__ int    g_topk[10][1024];
__device__ int    g_eq[10][4096];
__device__ float4 g_pbox[NIMG][MPROP];
__device__ float  g_pscore[NIMG][MPROP];
__device__ float4 g_sbox[NIMG][MPROP];
__device__ float  g_sscore[NIMG][MPROP];

// ---------------------------------------------------------------------------
// helpers (sm_80-era PTX only)
// ---------------------------------------------------------------------------
__device__ __forceinline__ uint32_t smem_u32(const void* p) {
    uint32_t a;
    asm("{ .reg .u64 t; cvta.to.shared.u64 t, %1; cvt.u32.u64 %0, t; }" : "=r"(a) : "l"(p));
    return a;
}
__device__ __forceinline__ void cp_async16(uint32_t dst, const void* src, unsigned srcsz) {
    asm volatile("cp.async.ca.shared.global [%0], [%1], 16, %2;"
                 :: "r"(dst), "l"(src), "r"(srcsz) : "memory");
}
#define CP_COMMIT() asm volatile("cp.async.commit_group;" ::: "memory")
#define CP_WAIT0()  asm volatile("cp.async.wait_group 0;" ::: "memory")

__device__ __forceinline__ void ldsm4(uint32_t* r, uint32_t addr) {
    asm volatile("ldmatrix.sync.aligned.m8n8.x4.shared.b16 {%0,%1,%2,%3}, [%4];"
                 : "=r"(r[0]), "=r"(r[1]), "=r"(r[2]), "=r"(r[3]) : "r"(addr));
}
// fp16 mma, fp32 accum. In-TC chain (RZ) — used only WITHIN a windowed chunk.
__device__ __forceinline__ void mma_f16(float* c, const uint32_t* a, uint32_t b0, uint32_t b1) {
    asm volatile("mma.sync.aligned.m16n8k16.row.col.f32.f16.f16.f32 "
                 "{%0,%1,%2,%3}, {%4,%5,%6,%7}, {%8,%9}, {%0,%1,%2,%3};"
                 : "+f"(c[0]), "+f"(c[1]), "+f"(c[2]), "+f"(c[3])
                 : "r"(a[0]), "r"(a[1]), "r"(a[2]), "r"(a[3]), "r"(b0), "r"(b1));
}
__device__ __forceinline__ void mma_f16_zero(float* d, const uint32_t* a, uint32_t b0, uint32_t b1) {
    asm volatile("mma.sync.aligned.m16n8k16.row.col.f32.f16.f16.f32 "
                 "{%0,%1,%2,%3}, {%4,%5,%6,%7}, {%8,%9}, {%10,%11,%12,%13};"
                 : "=f"(d[0]), "=f"(d[1]), "=f"(d[2]), "=f"(d[3])
                 : "r"(a[0]), "r"(a[1]), "r"(a[2]), "r"(a[3]), "r"(b0), "r"(b1),
                   "f"(0.f), "f"(0.f), "f"(0.f), "f"(0.f));
}

// fp16 2-split with scaled residual (avoids fp16 subnormals on small weights)
__device__ __forceinline__ void split2(float x, __half& h, __half& r) {
    h = __float2half_rn(x);
    r = __float2half_rn((x - __half2float(h)) * RSCALE);
}

// ---------------------------------------------------------------------------
// 0a) split weights: cw[co][ci][tap] -> g_spB[q][co][tap*256+ci]
// ---------------------------------------------------------------------------
__global__ void split_w_kernel(const float* __restrict__ cw) {
    int co = blockIdx.x, t = threadIdx.x;
#pragma unroll
    for (int it = 0; it < 9; it++) {
        float v = cw[co * 2304 + t * 9 + it];
        __half h, r;
        split2(v, h, r);
        int k = co * 2304 + it * 256 + t;
        g_spB[0][k] = h; g_spB[1][k] = r;
    }
}

// ---------------------------------------------------------------------------
// 0b) split + transpose features: feat[n][ci][pos] -> g_spA[q][n*MPOS+pos][ci]
// ---------------------------------------------------------------------------
__global__ __launch_bounds__(256)
void split_feat_kernel(const float* __restrict__ f0, const float* __restrict__ f1,
                       const float* __restrict__ f2, const float* __restrict__ f3,
                       const float* __restrict__ f4) {
    __shared__ float sm[64][65];
    int tile = blockIdx.x;
    int l = 0;
    while (l < 4 && tile >= c_ft[l + 1]) l++;
    const float* feat = (l == 0) ? f0 : (l == 1) ? f1 : (l == 2) ? f2 : (l == 3) ? f3 : f4;
    int hw = c_hw[l], pB = c_pbase[l];
    int p0 = (tile - c_ft[l]) * 64;
    int ci0 = blockIdx.y * 64;
    int n = blockIdx.z;
    int t = threadIdx.x;

    {
        int ci = t >> 2, v0 = t & 3;
        const float* src = feat + ((size_t)(n * 256 + ci0 + ci)) * hw;
        int s0 = v0 * 16;
#pragma unroll
        for (int j = 0; j < 16; j++) {
            int p = p0 + s0 + j;
            sm[ci][s0 + j] = (p < hw) ? src[p] : 0.f;
        }
    }
    __syncthreads();
    {
        int pos = t >> 2, g = t & 3;
        if (p0 + pos < hw) {
            union { __half h[16]; uint4 v[2]; } bh, br;
#pragma unroll
            for (int e = 0; e < 16; e++)
                split2(sm[g * 16 + e][pos], bh.h[e], br.h[e]);
            size_t drow = ((size_t)(n * MPOS + pB + p0 + pos)) * 256 + ci0 + g * 16;
            *(uint4*)(&g_spA[0][drow]) = bh.v[0]; *(uint4*)(&g_spA[0][drow + 8]) = bh.v[1];
            *(uint4*)(&g_spA[1][drow]) = br.v[0]; *(uint4*)(&g_spA[1][drow + 8]) = br.v[1];
        }
    }
}

// ---------------------------------------------------------------------------
// 1) conv3x3 as implicit GEMM on mma.sync (fp16 2-split scaled, 3 terms)
// ---------------------------------------------------------------------------
#define TILE_B 18432                 // 128 rows * 144 B
#define STAGE_BYTES (4 * TILE_B)     // 73728
#define CMMA_SMEM (1024 + 2 * STAGE_BYTES)   // 148480

struct GatherCtx {
    int n, pB, W, H, hw, flat, xx, yy, su, r;
    size_t browB;
};

__device__ __forceinline__ void prefetch_chunk(const GatherCtx& g, int c, uint32_t sbase) {
    const int tap = c >> 2, ci0 = (c & 3) * 64;
    const int dy = tap / 3 - 1, dx = tap % 3 - 1;
    const int k0 = tap * 256 + ci0;

    const int xs = g.xx + dx, ys = g.yy + dy;
    const bool valid = (g.flat < g.hw) && (xs >= 0) && (xs < g.W) && (ys >= 0) && (ys < g.H);
    const unsigned srcsz = valid ? 16u : 0u;
    const size_t srow = valid
        ? (((size_t)(g.n * MPOS + g.pB + g.flat + dy * g.W + dx)) * 256 + ci0) : (size_t)0;

    const uint32_t rowoff = (uint32_t)(g.r * 144);
#pragma unroll
    for (int q = 0; q < 2; q++) {
        const __half* gp = &g_spA[q][srow];
        const uint32_t db = sbase + q * TILE_B + rowoff;
#pragma unroll
        for (int v = 0; v < 4; v++) {
            int vec = g.su * 4 + v;
            cp_async16(db + vec * 16, gp + vec * 8, srcsz);
        }
    }
    const size_t br = g.browB + k0;
#pragma unroll
    for (int q = 0; q < 2; q++) {
        const __half* gp = &g_spB[q][br];
        const uint32_t db = sbase + (2 + q) * TILE_B + rowoff;
#pragma unroll
        for (int v = 0; v < 4; v++) {
            int vec = g.su * 4 + v;
            cp_async16(db + vec * 16, gp + vec * 8, 16u);
        }
    }
}

__global__ __launch_bounds__(256, 1)
void conv_mma_kernel(const float* __restrict__ cb) {
    extern __shared__ char smem[];
    const uint32_t sb = smem_u32(smem);
    const int tid = threadIdx.x;
    const int lane = tid & 31;
    const int wid = tid >> 5;
    const int mbase = (wid & 3) * 32;
    const int nbase = (wid >> 2) * 64;

    const int tile = blockIdx.x;
    const int half = blockIdx.y;
    const int n    = blockIdx.z;
    int l = 0;
    while (l < 4 && tile >= c_tstart[l + 1]) l++;
    const int H = c_H[l], W = c_W[l], hw = c_hw[l], pB = c_pbase[l];
    const int base = (tile - c_tstart[l]) * 128;
    const int ch0 = half * 128;

    if (tid < 128) ((float*)smem)[tid] = cb[ch0 + tid];

    GatherCtx g;
    g.n = n; g.pB = pB; g.W = W; g.H = H; g.hw = hw;
    g.r = tid >> 1; g.su = tid & 1;
    g.flat = base + g.r;
    g.yy = (g.flat < hw) ? (g.flat / W) : 0;
    g.xx = g.flat - g.yy * W;
    g.browB = ((size_t)(ch0 + g.r)) * 2304;

    float acc[2][8][4];
#pragma unroll
    for (int i = 0; i < 2; i++)
#pragma unroll
        for (int j = 0; j < 8; j++)
#pragma unroll
            for (int k = 0; k < 4; k++) acc[i][j][k] = 0.f;

    const int rowA0 = mbase + (lane & 7) + (lane & 8);
    const int colA  = ((lane >> 4) & 1) * 16;
    const int rowB0 = nbase + (lane & 7) + ((lane >> 1) & 8);
    const int colB  = ((lane >> 3) & 1) * 16;

    prefetch_chunk(g, 0, sb + 1024);
    CP_COMMIT();

#pragma unroll 1
    for (int c = 0; c < 36; c++) {
        const int st = c & 1;
        CP_WAIT0();
        __syncthreads();
        if (c + 1 < 36) {
            prefetch_chunk(g, c + 1, sb + 1024 + (st ^ 1) * STAGE_BYTES);
            CP_COMMIT();
        }
        const uint32_t sbase = sb + 1024 + st * STAGE_BYTES;
        const uint32_t Ah = sbase, Ar = sbase + TILE_B;
        const uint32_t Bh = sbase + 2 * TILE_B, Br = sbase + 3 * TILE_B;

        // ---- window 1: hh ----
        {
            float tmp[2][8][4];
#pragma unroll
            for (int ks = 0; ks < 4; ks++) {
                uint32_t afr[2][4];
#pragma unroll
                for (int mt = 0; mt < 2; mt++) {
                    int row = rowA0 + mt * 16;
                    ldsm4(afr[mt], Ah + row * 144 + ks * 32 + colA);
                }
#pragma unroll
                for (int t = 0; t < 4; t++) {
                    uint32_t bfr[4];
                    int row = rowB0 + t * 16;
                    ldsm4(bfr, Bh + row * 144 + ks * 32 + colB);
#pragma unroll
                    for (int mt = 0; mt < 2; mt++) {
                        if (ks == 0) {
                            mma_f16_zero(tmp[mt][t * 2],     afr[mt], bfr[0], bfr[1]);
                            mma_f16_zero(tmp[mt][t * 2 + 1], afr[mt], bfr[2], bfr[3]);
                        } else {
                            mma_f16(tmp[mt][t * 2],     afr[mt], bfr[0], bfr[1]);
                            mma_f16(tmp[mt][t * 2 + 1], afr[mt], bfr[2], bfr[3]);
                        }
                    }
                }
            }
#pragma unroll
            for (int mt = 0; mt < 2; mt++)
#pragma unroll
                for (int j = 0; j < 8; j++)
#pragma unroll
                    for (int kk = 0; kk < 4; kk++)
                        acc[mt][j][kk] += tmp[mt][j][kk];
        }

        // ---- window 2: h*r' + r'*h (scaled by 2^12), one shared chain ----
        {
            float tmp[2][8][4];
#pragma unroll
            for (int ks = 0; ks < 4; ks++) {
                uint32_t ah[2][4], ar[2][4];
#pragma unroll
                for (int mt = 0; mt < 2; mt++) {
                    int row = rowA0 + mt * 16;
                    ldsm4(ah[mt], Ah + row * 144 + ks * 32 + colA);
                    ldsm4(ar[mt], Ar + row * 144 + ks * 32 + colA);
                }
#pragma unroll
                for (int t = 0; t < 4; t++) {
                    uint32_t bh[4], br[4];
                    int row = rowB0 + t * 16;
                    ldsm4(bh, Bh + row * 144 + ks * 32 + colB);
                    ldsm4(br, Br + row * 144 + ks * 32 + colB);
#pragma unroll
                    for (int mt = 0; mt < 2; mt++) {
                        if (ks == 0) {
                            mma_f16_zero(tmp[mt][t * 2],     ah[mt], br[0], br[1]);
                            mma_f16_zero(tmp[mt][t * 2 + 1], ah[mt], br[2], br[3]);
                        } else {
                            mma_f16(tmp[mt][t * 2],     ah[mt], br[0], br[1]);
                            mma_f16(tmp[mt][t * 2 + 1], ah[mt], br[2], br[3]);
                        }
                        mma_f16(tmp[mt][t * 2],     ar[mt], bh[0], bh[1]);
                        mma_f16(tmp[mt][t * 2 + 1], ar[mt], bh[2], bh[3]);
                    }
                }
            }
#pragma unroll
            for (int mt = 0; mt < 2; mt++)
#pragma unroll
                for (int j = 0; j < 8; j++)
#pragma unroll
                    for (int kk = 0; kk < 4; kk++)
                        acc[mt][j][kk] = fmaf(tmp[mt][j][kk], RINV, acc[mt][j][kk]);
        }
    }

    // epilogue: bias + relu, write g_t[pos][c]
    const float* bias = (const float*)smem;
#pragma unroll
    for (int mt = 0; mt < 2; mt++) {
#pragma unroll
        for (int nt = 0; nt < 8; nt++) {
            int nn = nbase + nt * 8 + (lane & 3) * 2;
            float bn0 = bias[nn], bn1 = bias[nn + 1];
#pragma unroll
            for (int h2 = 0; h2 < 2; h2++) {
                int m = mbase + mt * 16 + (lane >> 2) + h2 * 8;
                int fl = base + m;
                if (fl < hw) {
                    float v0 = fmaxf(acc[mt][nt][h2 * 2 + 0] + bn0, 0.f);
                    float v1 = fmaxf(acc[mt][nt][h2 * 2 + 1] + bn1, 0.f);
                    *(float2*)&g_t[((size_t)(n * MPOS + pB + fl)) * 256 + ch0 + nn] =
                        make_float2(v0, v1);
                }
            }
        }
    }
}

// ---------------------------------------------------------------------------
// 2) 1x1 heads
// ---------------------------------------------------------------------------
__global__ void head1x1_kernel(const float* __restrict__ ow, const float* __restrict__ ob,
                               const float* __restrict__ dw, const float* __restrict__ db,
                               int HW, int pB, int aB) {
    __shared__ float w2[15 * 256];
    __shared__ float b2[15];
    const int t = threadIdx.x;
    for (int i = t; i < 3 * 256; i += 128) w2[i] = ow[i];
    for (int i = t; i < 12 * 256; i += 128) w2[768 + i] = dw[i];
    if (t < 3) b2[t] = ob[t];
    else if (t < 15) b2[t] = db[t - 3];
    __syncthreads();

    int pos = blockIdx.x * 128 + t;
    int n   = blockIdx.y;
    if (pos >= HW) return;

    const float4* trow = (const float4*)(g_t + ((size_t)(n * MPOS + pB + pos)) * 256);
    float acc[15];
#pragma unroll
    for (int o = 0; o < 15; o++) acc[o] = 0.f;

#pragma unroll 4
    for (int c4 = 0; c4 < 64; c4++) {
        float4 tv = trow[c4];
#pragma unroll
        for (int o = 0; o < 15; o++) {
            const float* wr = &w2[o * 256 + c4 * 4];
            acc[o] += tv.x * wr[0] + tv.y * wr[1] + tv.z * wr[2] + tv.w * wr[3];
        }
    }
    size_t ob_ = (size_t)n * MALL;
    int m = aB + pos * 3;
#pragma unroll
    for (int a = 0; a < 3; a++) {
        g_logits[ob_ + m + a] = acc[a] + b2[a];
#pragma unroll
        for (int d = 0; d < 4; d++)
            g_deltas[(ob_ + m + a) * 4 + d] = acc[3 + a * 4 + d] + b2[3 + a * 4 + d];
    }
}

// ---------------------------------------------------------------------------
// 3) per-(image,level) exact top-k — 1024 threads
// ---------------------------------------------------------------------------
__device__ __forceinline__ unsigned flipf(float f) {
    unsigned u = __float_as_uint(f);
    return (u & 0x80000000u) ? ~u : (u | 0x80000000u);
}

__global__ __launch_bounds__(1024)
void topk_kernel() {
    const int blk = blockIdx.x;
    const int n = blk / 5, l = blk % 5;
    const int NE = c_hwa[l];
    const int K  = c_k[l];
    const float* sc = g_logits + (size_t)n * MALL + c_abase[l];

    __shared__ unsigned hist[2048];
    __shared__ unsigned long long sortbuf[1024];
    __shared__ unsigned sB1, sB2, sB3, sNeed, sCntGt, sCntEq;
    const int t = threadIdx.x;

    for (int i = t; i < 2048; i += 1024) hist[i] = 0;
    __syncthreads();
    for (int i = t; i < NE; i += 1024) atomicAdd(&hist[flipf(sc[i]) >> 21], 1u);
    __syncthreads();
    if (t == 0) {
        unsigned acc = 0; int b = 2047;
        for (; b >= 0; b--) { unsigned h = hist[b]; if (acc + h >= (unsigned)K) break; acc += h; }
        sB1 = (unsigned)b; sNeed = (unsigned)K - acc;
    }
    __syncthreads();
    unsigned B1 = sB1, need1 = sNeed;

    for (int i = t; i < 2048; i += 1024) hist[i] = 0;
    __syncthreads();
    for (int i = t; i < NE; i += 1024) {
        unsigned k = flipf(sc[i]);
        if ((k >> 21) == B1) atomicAdd(&hist[(k >> 10) & 0x7FFu], 1u);
    }
    __syncthreads();
    if (t == 0) {
        unsigned acc = 0; int b = 2047;
        for (; b >= 0; b--) { unsigned h = hist[b]; if (acc + h >= need1) break; acc += h; }
        sB2 = (unsigned)b; sNeed = need1 - acc;
    }
    __syncthreads();
    unsigned B2 = sB2, need2 = sNeed;
    unsigned hi22 = (B1 << 11) | B2;

    for (int i = t; i < 1024; i += 1024) hist[i] = 0;
    __syncthreads();
    for (int i = t; i < NE; i += 1024) {
        unsigned k = flipf(sc[i]);
        if ((k >> 10) == hi22) atomicAdd(&hist[k & 0x3FFu], 1u);
    }
    __syncthreads();
    if (t == 0) {
        unsigned acc = 0; int b = 1023;
        for (; b >= 0; b--) { unsigned h = hist[b]; if (acc + h >= need2) break; acc += h; }
        sB3 = (unsigned)b; sNeed = need2 - acc;
        sCntGt = 0; sCntEq = 0;
    }
    __syncthreads();
    unsigned T = (B1 << 21) | (B2 << 10) | sB3;

    for (int i = t; i < NE; i += 1024) {
        unsigned k = flipf(sc[i]);
        if (k > T) {
            int s = (int)atomicAdd(&sCntGt, 1u);
            g_topk[blk][s] = i;
        } else if (k == T) {
            int e = (int)atomicAdd(&sCntEq, 1u);
            if (e < 4096) g_eq[blk][e] = i;
        }
    }
    __syncthreads();
    if (t == 0) {
        int base = (int)sCntGt;
        int rem  = K - base;
        int ne   = (int)sCntEq; if (ne > 4096) ne = 4096;
        for (int r2 = 0; r2 < rem; r2++) {
            int best = 0x7FFFFFFF, bj = -1;
            for (int j = 0; j < ne; j++)
                if (g_eq[blk][j] < best) { best = g_eq[blk][j]; bj = j; }
            if (bj >= 0) { g_topk[blk][base + r2] = best; g_eq[blk][bj] = 0x7FFFFFFF; }
        }
    }
    __syncthreads();

    {
        unsigned long long comb = 0ull;
        if (t < K) {
            int idx = g_topk[blk][t];
            comb = ((unsigned long long)flipf(sc[idx]) << 32) | (unsigned)(~(unsigned)idx);
        }
        sortbuf[t] = comb;
    }
    for (unsigned k2 = 2; k2 <= 1024; k2 <<= 1) {
        for (unsigned j = k2 >> 1; j > 0; j >>= 1) {
            __syncthreads();
            unsigned i = t;
            unsigned ixj = i ^ j;
            if (ixj > i) {
                bool dir = ((i & k2) == 0);
                unsigned long long a = sortbuf[i], b = sortbuf[ixj];
                if ((a < b) == dir) { sortbuf[i] = b; sortbuf[ixj] = a; }
            }
        }
    }
    __syncthreads();
    if (t < K)
        g_topk[blk][t] = (int)(~(unsigned)(sortbuf[t] & 0xFFFFFFFFull));
}

// ---------------------------------------------------------------------------
// 4) decode
// ---------------------------------------------------------------------------
__global__ void decode_kernel() {
    int sid = blockIdx.x * 256 + threadIdx.x;
    if (sid >= NIMG * MPROP) return;
    int n = sid / MPROP, s = sid - n * MPROP;
    int l = s / 1000; if (l > 4) l = 4;
    int kl = s - c_sbase[l];
    int blk = n * 5 + l;
    int idx = g_topk[blk][kl];

    float score = g_logits[(size_t)n * MALL + c_abase[l] + idx];
    int pos = idx / 3, a = idx - pos * 3;
    int W = c_W[l];
    int yy = pos / W, xx = pos - yy * W;

    double size = (double)c_size[l];
    double ratio = (a == 0) ? 0.5 : ((a == 1) ? 1.0 : 2.0);
    double wd = sqrt(size * size / ratio);
    double hd = wd * ratio;

    float sx = (float)(xx * c_stride[l]);
    float sy = (float)(yy * c_stride[l]);
    float ax1 = sx + (float)(-wd * 0.5), ay1 = sy + (float)(-hd * 0.5);
    float ax2 = sx + (float)(wd * 0.5),  ay2 = sy + (float)(hd * 0.5);

    float w = ax2 - ax1, h = ay2 - ay1;
    float cx = ax1 + 0.5f * w, cy = ay1 + 0.5f * h;

    const float* dp = &g_deltas[((size_t)n * MALL + c_abase[l] + idx) * 4];
    const float CLAMP = (float)4.135166556742356;
    float dwv = fminf(dp[2], CLAMP);
    float dhv = fminf(dp[3], CLAMP);

    float pcx = dp[0] * w + cx, pcy = dp[1] * h + cy;
    float pw = expf(dwv) * w, ph = expf(dhv) * h;

    float x1 = pcx - 0.5f * pw, y1 = pcy - 0.5f * ph;
    float x2 = pcx + 0.5f * pw, y2 = pcy + 0.5f * ph;
    x1 = fminf(fmaxf(x1, 0.f), 1216.f);
    x2 = fminf(fmaxf(x2, 0.f), 1216.f);
    y1 = fminf(fmaxf(y1, 0.f), 800.f);
    y2 = fminf(fmaxf(y2, 0.f), 800.f);

    bool valid = ((x2 - x1) > 0.f) && ((y2 - y1) > 0.f);
    g_pbox[n][s] = make_float4(x1, y1, x2, y2);
    g_pscore[n][s] = valid ? score : NEG_INF;
}

// ---------------------------------------------------------------------------
// 5a) sort pooled proposals by (score desc, idx asc)
// ---------------------------------------------------------------------------
__global__ __launch_bounds__(1024)
void sort_kernel() {
    extern __shared__ unsigned long long sbuf[];
    const int n = blockIdx.x;
    const int t = threadIdx.x;

    for (int i = t; i < NSORT; i += 1024) {
        unsigned long long key = 0ull;
        if (i < MPROP) {
            float s = g_pscore[n][i];
            key = ((unsigned long long)flipf(s) << 32) | (unsigned)(~(unsigned)i);
        }
        sbuf[i] = key;
    }
    for (unsigned k2 = 2; k2 <= NSORT; k2 <<= 1) {
        for (unsigned j = k2 >> 1; j > 0; j >>= 1) {
            __syncthreads();
            for (unsigned i = t; i < NSORT; i += 1024) {
                unsigned ixj = i ^ j;
                if (ixj > i) {
                    bool dir = ((i & k2) == 0);
                    unsigned long long a = sbuf[i], b = sbuf[ixj];
                    if ((a < b) == dir) { sbuf[i] = b; sbuf[ixj] = a; }
                }
            }
        }
    }
    __syncthreads();
    for (int r = t; r < MPROP; r += 1024) {
        unsigned idx = ~(unsigned)(sbuf[r] & 0xFFFFFFFFull);
        g_sbox[n][r]   = g_pbox[n][idx];
        g_sscore[n][r] = g_pscore[n][idx];
    }
}

// ---------------------------------------------------------------------------
// 5b) fused NMS scan: boxes in smem, on-the-fly IoU suppression, ffs skipping
// ---------------------------------------------------------------------------
#define SCAN_SMEM (MPROP * 16 + MPROP * 4 + NW * 4 + 64)

__global__ __launch_bounds__(1024)
void scan_kernel(float* __restrict__ out) {
    extern __shared__ char sm[];
    float4*   sbox    = (float4*)sm;                        // [MPROP]
    float*    ssc     = (float*)(sm + MPROP * 16);          // [MPROP]
    unsigned* removed = (unsigned*)(sm + MPROP * 20);       // [NW]
    __shared__ int s_sel;
    __shared__ int s_vcnt;

    const int n = blockIdx.x;
    const int t = threadIdx.x;

    for (int i = t; i < MPROP; i += 1024) {
        sbox[i] = g_sbox[n][i];
        ssc[i]  = g_sscore[n][i];
    }
    for (int w = t; w < NW; w += 1024) removed[w] = 0u;
    if (t == 0) s_vcnt = 0;
    __syncthreads();
    // count valid (scores sorted desc; valid iff > NEG_INF/2)
    {
        int cnt = 0;
        for (int i = t; i < MPROP; i += 1024)
            if (ssc[i] > -5e8f) cnt++;
        // warp + block reduce via atomic (once per thread)
        if (cnt) atomicAdd(&s_vcnt, cnt);
    }
    __syncthreads();
    const int vlimit = s_vcnt;

    int k = 0;
    int cur = 0;      // meaningful on t==0 only
    while (k < POSTK) {
        if (t == 0) {
            int i = cur;
            int sel = -1;
            while (i < vlimit) {
                unsigned w = ~removed[i >> 5];
                w >>= (i & 31);
                if (w) { sel = i + (__ffs(w) - 1); break; }
                i = ((i >> 5) + 1) << 5;
            }
            if (sel >= vlimit) sel = -1;
            s_sel = sel;
        }
        __syncthreads();
        const int sel = s_sel;
        if (sel < 0) break;

        const float4 b = sbox[sel];
        const float a1 = (b.z - b.x) * (b.w - b.y);
        for (int j = t; j < MPROP; j += 1024) {
            float4 c = sbox[j];
            float lx = fmaxf(b.x, c.x), ly = fmaxf(b.y, c.y);
            float rx = fminf(b.z, c.z), ry = fminf(b.w, c.w);
            float iw = fmaxf(rx - lx, 0.f), ih = fmaxf(ry - ly, 0.f);
            float inter = iw * ih;
            float a2 = (c.z - c.x) * (c.w - c.y);
            float iou = inter / fmaxf(a1 + a2 - inter, 1e-9f);
            if (iou > 0.7f) atomicOr(&removed[j >> 5], 1u << (j & 31));
        }
        if (t == 0) {
            float* o = out + ((size_t)n * POSTK + k) * 5;
            o[0] = b.x; o[1] = b.y; o[2] = b.z; o[3] = b.w; o[4] = ssc[sel];
            cur = sel + 1;
        }
        k++;
        __syncthreads();
    }
    // pad remaining rows
    for (int r = k + t; r < POSTK; r += 1024) {
        float* o = out + ((size_t)n * POSTK + r) * 5;
        o[0] = 0.f; o[1] = 0.f; o[2] = 0.f; o[3] = 0.f; o[4] = NEG_INF;
    }
}

// ---------------------------------------------------------------------------
// launch
// ---------------------------------------------------------------------------
extern "C" void kernel_launch(void* const* d_in, const int* in_sizes, int n_in,
                              void* d_out, int out_size) {
    const float* feats[5];
    for (int i = 0; i < 5; i++) feats[i] = (const float*)d_in[i];
    const float* conv_w  = (const float*)d_in[5];
    const float* conv_b  = (const float*)d_in[6];
    const float* obj_w   = (const float*)d_in[7];
    const float* obj_b   = (const float*)d_in[8];
    const float* delta_w = (const float*)d_in[9];
    const float* delta_b = (const float*)d_in[10];
    float* out = (float*)d_out;

    static const int HWh[5] = {60800, 15200, 3800, 950, 247};
    static const int pBh[5] = {0, 60800, 76000, 79800, 80750};
    static const int aBh[5] = {0, 182400, 228000, 239400, 242250};

    cudaFuncSetAttribute(conv_mma_kernel, cudaFuncAttributeMaxDynamicSharedMemorySize, CMMA_SMEM);
    cudaFuncSetAttribute(sort_kernel, cudaFuncAttributeMaxDynamicSharedMemorySize, NSORT * 8);
    cudaFuncSetAttribute(scan_kernel, cudaFuncAttributeMaxDynamicSharedMemorySize, SCAN_SMEM);

    split_w_kernel<<<256, 256>>>(conv_w);
    {
        dim3 grid(1267, 4, NIMG);
        split_feat_kernel<<<grid, 256>>>(feats[0], feats[1], feats[2], feats[3], feats[4]);
    }
    {
        dim3 grid(634, 2, NIMG);
        conv_mma_kernel<<<grid, 256, CMMA_SMEM>>>(conv_b);
    }
    for (int l = 0; l < 5; l++) {
        dim3 grid((HWh[l] + 127) / 128, NIMG);
        head1x1_kernel<<<grid, 128>>>(obj_w, obj_b, delta_w, delta_b, HWh[l], pBh[l], aBh[l]);
    }
    topk_kernel<<<10, 1024>>>();
    decode_kernel<<<(NIMG * MPROP + 255) / 256, 256>>>();

    sort_kernel<<<NIMG, 1024, NSORT * 8>>>();
    scan_kernel<<<NIMG, 1024, SCAN_SMEM>>>(out);
}

// round 14
// speedup vs baseline: 1.5549x; 1.5549x over previous
#include <cuda_runtime.h>
#include <cuda_bf16.h>
#include <cuda_fp16.h>
#include <math.h>
#include <stdint.h>

#define NIMG 2
#define MALL 242991
#define MPOS 80997
#define MPROP 4741
#define POSTK 1000
#define NEG_INF (-1e9f)
#define NW 149
#define NSORT 8192
#define RSCALE 4096.0f
#define RINV   2.44140625e-4f   // 1/4096 exact

__constant__ int c_H[5]      = {200, 100, 50, 25, 13};
__constant__ int c_W[5]      = {304, 152, 76, 38, 19};
__constant__ int c_stride[5] = {4, 8, 16, 32, 64};
__constant__ int c_size[5]   = {32, 64, 128, 256, 512};
__constant__ int c_hw[5]     = {60800, 15200, 3800, 950, 247};
__constant__ int c_hwa[5]    = {182400, 45600, 11400, 2850, 741};
__constant__ int c_abase[5]  = {0, 182400, 228000, 239400, 242250};
__constant__ int c_pbase[5]  = {0, 60800, 76000, 79800, 80750};
__constant__ int c_k[5]      = {1000, 1000, 1000, 1000, 741};
__constant__ int c_sbase[5]  = {0, 1000, 2000, 3000, 4000};
__constant__ int c_tstart[6] = {0, 475, 594, 624, 632, 634};     // ceil(hw/128) cum
__constant__ int c_ft[6]     = {0, 950, 1188, 1248, 1263, 1267}; // ceil(hw/64) cum

// ---------------------------------------------------------------------------
// Device scratch
// ---------------------------------------------------------------------------
__device__ __half g_spA[2][(size_t)NIMG * MPOS * 256];  // [q][n*MPOS+pos][ci]  q=0:h q=1:r*4096
__device__ __half g_spB[2][256 * 2304];                 // [q][co][tap*256+ci]
__device__ float  g_t[(size_t)NIMG * MPOS * 256];
__device__ float  g_logits[NIMG * MALL];
__device__ float  g_deltas[(size_t)NIMG * MALL * 4];
__device__ int    g_topk[10][1024];
__device__ int    g_eq[10][4096];
__device__ float4 g_pbox[NIMG][MPROP];
__device__ float  g_pscore[NIMG][MPROP];
__device__ float4 g_sbox[NIMG][MPROP];
__device__ float  g_sscore[NIMG][MPROP];
__device__ unsigned g_mask[NIMG][MPROP][NW];

// ---------------------------------------------------------------------------
// helpers (sm_80-era PTX only)
// ---------------------------------------------------------------------------
__device__ __forceinline__ uint32_t smem_u32(const void* p) {
    uint32_t a;
    asm("{ .reg .u64 t; cvta.to.shared.u64 t, %1; cvt.u32.u64 %0, t; }" : "=r"(a) : "l"(p));
    return a;
}
__device__ __forceinline__ void cp_async16(uint32_t dst, const void* src, unsigned srcsz) {
    asm volatile("cp.async.ca.shared.global [%0], [%1], 16, %2;"
                 :: "r"(dst), "l"(src), "r"(srcsz) : "memory");
}
#define CP_COMMIT() asm volatile("cp.async.commit_group;" ::: "memory")
#define CP_WAIT0()  asm volatile("cp.async.wait_group 0;" ::: "memory")

__device__ __forceinline__ void ldsm4(uint32_t* r, uint32_t addr) {
    asm volatile("ldmatrix.sync.aligned.m8n8.x4.shared.b16 {%0,%1,%2,%3}, [%4];"
                 : "=r"(r[0]), "=r"(r[1]), "=r"(r[2]), "=r"(r[3]) : "r"(addr));
}
// fp16 mma, fp32 accum. In-TC chain (RZ) — used only WITHIN a windowed chunk.
__device__ __forceinline__ void mma_f16(float* c, const uint32_t* a, uint32_t b0, uint32_t b1) {
    asm volatile("mma.sync.aligned.m16n8k16.row.col.f32.f16.f16.f32 "
                 "{%0,%1,%2,%3}, {%4,%5,%6,%7}, {%8,%9}, {%0,%1,%2,%3};"
                 : "+f"(c[0]), "+f"(c[1]), "+f"(c[2]), "+f"(c[3])
                 : "r"(a[0]), "r"(a[1]), "r"(a[2]), "r"(a[3]), "r"(b0), "r"(b1));
}
__device__ __forceinline__ void mma_f16_zero(float* d, const uint32_t* a, uint32_t b0, uint32_t b1) {
    asm volatile("mma.sync.aligned.m16n8k16.row.col.f32.f16.f16.f32 "
                 "{%0,%1,%2,%3}, {%4,%5,%6,%7}, {%8,%9}, {%10,%11,%12,%13};"
                 : "=f"(d[0]), "=f"(d[1]), "=f"(d[2]), "=f"(d[3])
                 : "r"(a[0]), "r"(a[1]), "r"(a[2]), "r"(a[3]), "r"(b0), "r"(b1),
                   "f"(0.f), "f"(0.f), "f"(0.f), "f"(0.f));
}

// fp16 2-split with scaled residual (avoids fp16 subnormals on small weights)
__device__ __forceinline__ void split2(float x, __half& h, __half& r) {
    h = __float2half_rn(x);
    r = __float2half_rn((x - __half2float(h)) * RSCALE);
}

// ---------------------------------------------------------------------------
// 0a) split weights: cw[co][ci][tap] -> g_spB[q][co][tap*256+ci]
// ---------------------------------------------------------------------------
__global__ void split_w_kernel(const float* __restrict__ cw) {
    int co = blockIdx.x, t = threadIdx.x;
#pragma unroll
    for (int it = 0; it < 9; it++) {
        float v = cw[co * 2304 + t * 9 + it];
        __half h, r;
        split2(v, h, r);
        int k = co * 2304 + it * 256 + t;
        g_spB[0][k] = h; g_spB[1][k] = r;
    }
}

// ---------------------------------------------------------------------------
// 0b) split + transpose features: feat[n][ci][pos] -> g_spA[q][n*MPOS+pos][ci]
// ---------------------------------------------------------------------------
__global__ __launch_bounds__(256)
void split_feat_kernel(const float* __restrict__ f0, const float* __restrict__ f1,
                       const float* __restrict__ f2, const float* __restrict__ f3,
                       const float* __restrict__ f4) {
    __shared__ float sm[64][65];
    int tile = blockIdx.x;
    int l = 0;
    while (l < 4 && tile >= c_ft[l + 1]) l++;
    const float* feat = (l == 0) ? f0 : (l == 1) ? f1 : (l == 2) ? f2 : (l == 3) ? f3 : f4;
    int hw = c_hw[l], pB = c_pbase[l];
    int p0 = (tile - c_ft[l]) * 64;
    int ci0 = blockIdx.y * 64;
    int n = blockIdx.z;
    int t = threadIdx.x;

    {
        int ci = t >> 2, v0 = t & 3;
        const float* src = feat + ((size_t)(n * 256 + ci0 + ci)) * hw;
        int s0 = v0 * 16;
#pragma unroll
        for (int j = 0; j < 16; j++) {
            int p = p0 + s0 + j;
            sm[ci][s0 + j] = (p < hw) ? src[p] : 0.f;
        }
    }
    __syncthreads();
    {
        int pos = t >> 2, g = t & 3;
        if (p0 + pos < hw) {
            union { __half h[16]; uint4 v[2]; } bh, br;
#pragma unroll
            for (int e = 0; e < 16; e++)
                split2(sm[g * 16 + e][pos], bh.h[e], br.h[e]);
            size_t drow = ((size_t)(n * MPOS + pB + p0 + pos)) * 256 + ci0 + g * 16;
            *(uint4*)(&g_spA[0][drow]) = bh.v[0]; *(uint4*)(&g_spA[0][drow + 8]) = bh.v[1];
            *(uint4*)(&g_spA[1][drow]) = br.v[0]; *(uint4*)(&g_spA[1][drow + 8]) = br.v[1];
        }
    }
}

// ---------------------------------------------------------------------------
// 1) conv3x3 as implicit GEMM on mma.sync (fp16 2-split scaled, 3 terms)
// ---------------------------------------------------------------------------
#define TILE_B 18432                 // 128 rows * 144 B
#define STAGE_BYTES (4 * TILE_B)     // 73728
#define CMMA_SMEM (1024 + 2 * STAGE_BYTES)   // 148480

struct GatherCtx {
    int n, pB, W, H, hw, flat, xx, yy, su, r;
    size_t browB;
};

__device__ __forceinline__ void prefetch_chunk(const GatherCtx& g, int c, uint32_t sbase) {
    const int tap = c >> 2, ci0 = (c & 3) * 64;
    const int dy = tap / 3 - 1, dx = tap % 3 - 1;
    const int k0 = tap * 256 + ci0;

    const int xs = g.xx + dx, ys = g.yy + dy;
    const bool valid = (g.flat < g.hw) && (xs >= 0) && (xs < g.W) && (ys >= 0) && (ys < g.H);
    const unsigned srcsz = valid ? 16u : 0u;
    const size_t srow = valid
        ? (((size_t)(g.n * MPOS + g.pB + g.flat + dy * g.W + dx)) * 256 + ci0) : (size_t)0;

    const uint32_t rowoff = (uint32_t)(g.r * 144);
#pragma unroll
    for (int q = 0; q < 2; q++) {
        const __half* gp = &g_spA[q][srow];
        const uint32_t db = sbase + q * TILE_B + rowoff;
#pragma unroll
        for (int v = 0; v < 4; v++) {
            int vec = g.su * 4 + v;
            cp_async16(db + vec * 16, gp + vec * 8, srcsz);
        }
    }
    const size_t br = g.browB + k0;
#pragma unroll
    for (int q = 0; q < 2; q++) {
        const __half* gp = &g_spB[q][br];
        const uint32_t db = sbase + (2 + q) * TILE_B + rowoff;
#pragma unroll
        for (int v = 0; v < 4; v++) {
            int vec = g.su * 4 + v;
            cp_async16(db + vec * 16, gp + vec * 8, 16u);
        }
    }
}

__global__ __launch_bounds__(256, 1)
void conv_mma_kernel(const float* __restrict__ cb) {
    extern __shared__ char smem[];
    const uint32_t sb = smem_u32(smem);
    const int tid = threadIdx.x;
    const int lane = tid & 31;
    const int wid = tid >> 5;
    const int mbase = (wid & 3) * 32;
    const int nbase = (wid >> 2) * 64;

    const int tile = blockIdx.x;
    const int half = blockIdx.y;
    const int n    = blockIdx.z;
    int l = 0;
    while (l < 4 && tile >= c_tstart[l + 1]) l++;
    const int H = c_H[l], W = c_W[l], hw = c_hw[l], pB = c_pbase[l];
    const int base = (tile - c_tstart[l]) * 128;
    const int ch0 = half * 128;

    if (tid < 128) ((float*)smem)[tid] = cb[ch0 + tid];

    GatherCtx g;
    g.n = n; g.pB = pB; g.W = W; g.H = H; g.hw = hw;
    g.r = tid >> 1; g.su = tid & 1;
    g.flat = base + g.r;
    g.yy = (g.flat < hw) ? (g.flat / W) : 0;
    g.xx = g.flat - g.yy * W;
    g.browB = ((size_t)(ch0 + g.r)) * 2304;

    float acc[2][8][4];
#pragma unroll
    for (int i = 0; i < 2; i++)
#pragma unroll
        for (int j = 0; j < 8; j++)
#pragma unroll
            for (int k = 0; k < 4; k++) acc[i][j][k] = 0.f;

    const int rowA0 = mbase + (lane & 7) + (lane & 8);
    const int colA  = ((lane >> 4) & 1) * 16;
    const int rowB0 = nbase + (lane & 7) + ((lane >> 1) & 8);
    const int colB  = ((lane >> 3) & 1) * 16;

    prefetch_chunk(g, 0, sb + 1024);
    CP_COMMIT();

#pragma unroll 1
    for (int c = 0; c < 36; c++) {
        const int st = c & 1;
        CP_WAIT0();
        __syncthreads();
        if (c + 1 < 36) {
            prefetch_chunk(g, c + 1, sb + 1024 + (st ^ 1) * STAGE_BYTES);
            CP_COMMIT();
        }
        const uint32_t sbase = sb + 1024 + st * STAGE_BYTES;
        const uint32_t Ah = sbase, Ar = sbase + TILE_B;
        const uint32_t Bh = sbase + 2 * TILE_B, Br = sbase + 3 * TILE_B;

        // ---- window 1: hh ----
        {
            float tmp[2][8][4];
#pragma unroll
            for (int ks = 0; ks < 4; ks++) {
                uint32_t afr[2][4];
#pragma unroll
                for (int mt = 0; mt < 2; mt++) {
                    int row = rowA0 + mt * 16;
                    ldsm4(afr[mt], Ah + row * 144 + ks * 32 + colA);
                }
#pragma unroll
                for (int t = 0; t < 4; t++) {
                    uint32_t bfr[4];
                    int row = rowB0 + t * 16;
                    ldsm4(bfr, Bh + row * 144 + ks * 32 + colB);
#pragma unroll
                    for (int mt = 0; mt < 2; mt++) {
                        if (ks == 0) {
                            mma_f16_zero(tmp[mt][t * 2],     afr[mt], bfr[0], bfr[1]);
                            mma_f16_zero(tmp[mt][t * 2 + 1], afr[mt], bfr[2], bfr[3]);
                        } else {
                            mma_f16(tmp[mt][t * 2],     afr[mt], bfr[0], bfr[1]);
                            mma_f16(tmp[mt][t * 2 + 1], afr[mt], bfr[2], bfr[3]);
                        }
                    }
                }
            }
#pragma unroll
            for (int mt = 0; mt < 2; mt++)
#pragma unroll
                for (int j = 0; j < 8; j++)
#pragma unroll
                    for (int kk = 0; kk < 4; kk++)
                        acc[mt][j][kk] += tmp[mt][j][kk];
        }

        // ---- window 2: h*r' + r'*h (scaled by 2^12), one shared chain ----
        {
            float tmp[2][8][4];
#pragma unroll
            for (int ks = 0; ks < 4; ks++) {
                uint32_t ah[2][4], ar[2][4];
#pragma unroll
                for (int mt = 0; mt < 2; mt++) {
                    int row = rowA0 + mt * 16;
                    ldsm4(ah[mt], Ah + row * 144 + ks * 32 + colA);
                    ldsm4(ar[mt], Ar + row * 144 + ks * 32 + colA);
                }
#pragma unroll
                for (int t = 0; t < 4; t++) {
                    uint32_t bh[4], br[4];
                    int row = rowB0 + t * 16;
                    ldsm4(bh, Bh + row * 144 + ks * 32 + colB);
                    ldsm4(br, Br + row * 144 + ks * 32 + colB);
#pragma unroll
                    for (int mt = 0; mt < 2; mt++) {
                        if (ks == 0) {
                            mma_f16_zero(tmp[mt][t * 2],     ah[mt], br[0], br[1]);
                            mma_f16_zero(tmp[mt][t * 2 + 1], ah[mt], br[2], br[3]);
                        } else {
                            mma_f16(tmp[mt][t * 2],     ah[mt], br[0], br[1]);
                            mma_f16(tmp[mt][t * 2 + 1], ah[mt], br[2], br[3]);
                        }
                        mma_f16(tmp[mt][t * 2],     ar[mt], bh[0], bh[1]);
                        mma_f16(tmp[mt][t * 2 + 1], ar[mt], bh[2], bh[3]);
                    }
                }
            }
#pragma unroll
            for (int mt = 0; mt < 2; mt++)
#pragma unroll
                for (int j = 0; j < 8; j++)
#pragma unroll
                    for (int kk = 0; kk < 4; kk++)
                        acc[mt][j][kk] = fmaf(tmp[mt][j][kk], RINV, acc[mt][j][kk]);
        }
    }

    // epilogue: bias + relu, write g_t[pos][c]
    const float* bias = (const float*)smem;
#pragma unroll
    for (int mt = 0; mt < 2; mt++) {
#pragma unroll
        for (int nt = 0; nt < 8; nt++) {
            int nn = nbase + nt * 8 + (lane & 3) * 2;
            float bn0 = bias[nn], bn1 = bias[nn + 1];
#pragma unroll
            for (int h2 = 0; h2 < 2; h2++) {
                int m = mbase + mt * 16 + (lane >> 2) + h2 * 8;
                int fl = base + m;
                if (fl < hw) {
                    float v0 = fmaxf(acc[mt][nt][h2 * 2 + 0] + bn0, 0.f);
                    float v1 = fmaxf(acc[mt][nt][h2 * 2 + 1] + bn1, 0.f);
                    *(float2*)&g_t[((size_t)(n * MPOS + pB + fl)) * 256 + ch0 + nn] =
                        make_float2(v0, v1);
                }
            }
        }
    }
}

// ---------------------------------------------------------------------------
// 2) 1x1 heads — merged single launch over all levels (128-pos tiles)
// ---------------------------------------------------------------------------
__global__ void head1x1_kernel(const float* __restrict__ ow, const float* __restrict__ ob,
                               const float* __restrict__ dw, const float* __restrict__ db) {
    __shared__ float w2[15 * 256];
    __shared__ float b2[15];
    const int t = threadIdx.x;
    for (int i = t; i < 3 * 256; i += 128) w2[i] = ow[i];
    for (int i = t; i < 12 * 256; i += 128) w2[768 + i] = dw[i];
    if (t < 3) b2[t] = ob[t];
    else if (t < 15) b2[t] = db[t - 3];
    __syncthreads();

    const int tile = blockIdx.x;
    const int n    = blockIdx.y;
    int l = 0;
    while (l < 4 && tile >= c_tstart[l + 1]) l++;
    const int hw = c_hw[l], pB = c_pbase[l], aB = c_abase[l];
    const int pos = (tile - c_tstart[l]) * 128 + t;
    if (pos >= hw) return;

    const float4* trow = (const float4*)(g_t + ((size_t)(n * MPOS + pB + pos)) * 256);
    float acc[15];
#pragma unroll
    for (int o = 0; o < 15; o++) acc[o] = 0.f;

#pragma unroll 4
    for (int c4 = 0; c4 < 64; c4++) {
        float4 tv = trow[c4];
#pragma unroll
        for (int o = 0; o < 15; o++) {
            const float* wr = &w2[o * 256 + c4 * 4];
            acc[o] += tv.x * wr[0] + tv.y * wr[1] + tv.z * wr[2] + tv.w * wr[3];
        }
    }
    size_t ob_ = (size_t)n * MALL;
    int m = aB + pos * 3;
#pragma unroll
    for (int a = 0; a < 3; a++) {
        g_logits[ob_ + m + a] = acc[a] + b2[a];
#pragma unroll
        for (int d = 0; d < 4; d++)
            g_deltas[(ob_ + m + a) * 4 + d] = acc[3 + a * 4 + d] + b2[3 + a * 4 + d];
    }
}

// ---------------------------------------------------------------------------
// 3) per-(image,level) exact top-k — 512 threads
// ---------------------------------------------------------------------------
__device__ __forceinline__ unsigned flipf(float f) {
    unsigned u = __float_as_uint(f);
    return (u & 0x80000000u) ? ~u : (u | 0x80000000u);
}

__global__ __launch_bounds__(512)
void topk_kernel() {
    const int blk = blockIdx.x;
    const int n = blk / 5, l = blk % 5;
    const int NE = c_hwa[l];
    const int K  = c_k[l];
    const float* sc = g_logits + (size_t)n * MALL + c_abase[l];

    __shared__ unsigned hist[2048];
    __shared__ unsigned long long sortbuf[1024];
    __shared__ unsigned sB1, sB2, sB3, sNeed, sCntGt, sCntEq;
    const int t = threadIdx.x;

    for (int i = t; i < 2048; i += 512) hist[i] = 0;
    __syncthreads();
    for (int i = t; i < NE; i += 512) atomicAdd(&hist[flipf(sc[i]) >> 21], 1u);
    __syncthreads();
    if (t == 0) {
        unsigned acc = 0; int b = 2047;
        for (; b >= 0; b--) { unsigned h = hist[b]; if (acc + h >= (unsigned)K) break; acc += h; }
        sB1 = (unsigned)b; sNeed = (unsigned)K - acc;
    }
    __syncthreads();
    unsigned B1 = sB1, need1 = sNeed;

    for (int i = t; i < 2048; i += 512) hist[i] = 0;
    __syncthreads();
    for (int i = t; i < NE; i += 512) {
        unsigned k = flipf(sc[i]);
        if ((k >> 21) == B1) atomicAdd(&hist[(k >> 10) & 0x7FFu], 1u);
    }
    __syncthreads();
    if (t == 0) {
        unsigned acc = 0; int b = 2047;
        for (; b >= 0; b--) { unsigned h = hist[b]; if (acc + h >= need1) break; acc += h; }
        sB2 = (unsigned)b; sNeed = need1 - acc;
    }
    __syncthreads();
    unsigned B2 = sB2, need2 = sNeed;
    unsigned hi22 = (B1 << 11) | B2;

    for (int i = t; i < 1024; i += 512) hist[i] = 0;
    __syncthreads();
    for (int i = t; i < NE; i += 512) {
        unsigned k = flipf(sc[i]);
        if ((k >> 10) == hi22) atomicAdd(&hist[k & 0x3FFu], 1u);
    }
    __syncthreads();
    if (t == 0) {
        unsigned acc = 0; int b = 1023;
        for (; b >= 0; b--) { unsigned h = hist[b]; if (acc + h >= need2) break; acc += h; }
        sB3 = (unsigned)b; sNeed = need2 - acc;
        sCntGt = 0; sCntEq = 0;
    }
    __syncthreads();
    unsigned T = (B1 << 21) | (B2 << 10) | sB3;

    for (int i = t; i < NE; i += 512) {
        unsigned k = flipf(sc[i]);
        if (k > T) {
            int s = (int)atomicAdd(&sCntGt, 1u);
            g_topk[blk][s] = i;
        } else if (k == T) {
            int e = (int)atomicAdd(&sCntEq, 1u);
            if (e < 4096) g_eq[blk][e] = i;
        }
    }
    __syncthreads();
    if (t == 0) {
        int base = (int)sCntGt;
        int rem  = K - base;
        int ne   = (int)sCntEq; if (ne > 4096) ne = 4096;
        for (int r2 = 0; r2 < rem; r2++) {
            int best = 0x7FFFFFFF, bj = -1;
            for (int j = 0; j < ne; j++)
                if (g_eq[blk][j] < best) { best = g_eq[blk][j]; bj = j; }
            if (bj >= 0) { g_topk[blk][base + r2] = best; g_eq[blk][bj] = 0x7FFFFFFF; }
        }
    }
    __syncthreads();

    for (int s = t; s < 1024; s += 512) {
        unsigned long long comb = 0ull;
        if (s < K) {
            int idx = g_topk[blk][s];
            comb = ((unsigned long long)flipf(sc[idx]) << 32) | (unsigned)(~(unsigned)idx);
        }
        sortbuf[s] = comb;
    }
    for (unsigned k2 = 2; k2 <= 1024; k2 <<= 1) {
        for (unsigned j = k2 >> 1; j > 0; j >>= 1) {
            __syncthreads();
            for (unsigned i = t; i < 1024; i += 512) {
                unsigned ixj = i ^ j;
                if (ixj > i) {
                    bool dir = ((i & k2) == 0);
                    unsigned long long a = sortbuf[i], b = sortbuf[ixj];
                    if ((a < b) == dir) { sortbuf[i] = b; sortbuf[ixj] = a; }
                }
            }
        }
    }
    __syncthreads();
    for (int s = t; s < K; s += 512)
        g_topk[blk][s] = (int)(~(unsigned)(sortbuf[s] & 0xFFFFFFFFull));
}

// ---------------------------------------------------------------------------
// 4) decode
// ---------------------------------------------------------------------------
__global__ void decode_kernel() {
    int sid = blockIdx.x * 256 + threadIdx.x;
    if (sid >= NIMG * MPROP) return;
    int n = sid / MPROP, s = sid - n * MPROP;
    int l = s / 1000; if (l > 4) l = 4;
    int kl = s - c_sbase[l];
    int blk = n * 5 + l;
    int idx = g_topk[blk][kl];

    float score = g_logits[(size_t)n * MALL + c_abase[l] + idx];
    int pos = idx / 3, a = idx - pos * 3;
    int W = c_W[l];
    int yy = pos / W, xx = pos - yy * W;

    double size = (double)c_size[l];
    double ratio = (a == 0) ? 0.5 : ((a == 1) ? 1.0 : 2.0);
    double wd = sqrt(size * size / ratio);
    double hd = wd * ratio;

    float sx = (float)(xx * c_stride[l]);
    float sy = (float)(yy * c_stride[l]);
    float ax1 = sx + (float)(-wd * 0.5), ay1 = sy + (float)(-hd * 0.5);
    float ax2 = sx + (float)(wd * 0.5),  ay2 = sy + (float)(hd * 0.5);

    float w = ax2 - ax1, h = ay2 - ay1;
    float cx = ax1 + 0.5f * w, cy = ay1 + 0.5f * h;

    const float* dp = &g_deltas[((size_t)n * MALL + c_abase[l] + idx) * 4];
    const float CLAMP = (float)4.135166556742356;
    float dwv = fminf(dp[2], CLAMP);
    float dhv = fminf(dp[3], CLAMP);

    float pcx = dp[0] * w + cx, pcy = dp[1] * h + cy;
    float pw = expf(dwv) * w, ph = expf(dhv) * h;

    float x1 = pcx - 0.5f * pw, y1 = pcy - 0.5f * ph;
    float x2 = pcx + 0.5f * pw, y2 = pcy + 0.5f * ph;
    x1 = fminf(fmaxf(x1, 0.f), 1216.f);
    x2 = fminf(fmaxf(x2, 0.f), 1216.f);
    y1 = fminf(fmaxf(y1, 0.f), 800.f);
    y2 = fminf(fmaxf(y2, 0.f), 800.f);

    bool valid = ((x2 - x1) > 0.f) && ((y2 - y1) > 0.f);
    g_pbox[n][s] = make_float4(x1, y1, x2, y2);
    g_pscore[n][s] = valid ? score : NEG_INF;
}

// ---------------------------------------------------------------------------
// 5a) sort pooled proposals by (score desc, idx asc)
// ---------------------------------------------------------------------------
__global__ __launch_bounds__(1024)
void sort_kernel() {
    extern __shared__ unsigned long long sbuf[];
    const int n = blockIdx.x;
    const int t = threadIdx.x;

    for (int i = t; i < NSORT; i += 1024) {
        unsigned long long key = 0ull;
        if (i < MPROP) {
            float s = g_pscore[n][i];
            key = ((unsigned long long)flipf(s) << 32) | (unsigned)(~(unsigned)i);
        }
        sbuf[i] = key;
    }
    for (unsigned k2 = 2; k2 <= NSORT; k2 <<= 1) {
        for (unsigned j = k2 >> 1; j > 0; j >>= 1) {
            __syncthreads();
            for (unsigned i = t; i < NSORT; i += 1024) {
                unsigned ixj = i ^ j;
                if (ixj > i) {
                    bool dir = ((i & k2) == 0);
                    unsigned long long a = sbuf[i], b = sbuf[ixj];
                    if ((a < b) == dir) { sbuf[i] = b; sbuf[ixj] = a; }
                }
            }
        }
    }
    __syncthreads();
    for (int r = t; r < MPROP; r += 1024) {
        unsigned idx = ~(unsigned)(sbuf[r] & 0xFFFFFFFFull);
        g_sbox[n][r]   = g_pbox[n][idx];
        g_sscore[n][r] = g_pscore[n][idx];
    }
}

// ---------------------------------------------------------------------------
// 5b) suppression bitmask
// ---------------------------------------------------------------------------
__global__ __launch_bounds__(512)
void mask_kernel() {
    __shared__ float4 jb[128];
    const int n = blockIdx.z;
    const int tid = threadIdx.x;
    const int i = blockIdx.x * 128 + (tid & 127);
    const int wloc = tid >> 7;
    const int w = blockIdx.y * 4 + wloc;
    const int j0 = blockIdx.y * 128;

    if (tid < 128) {
        int j = j0 + tid;
        jb[tid] = (j < MPROP) ? g_sbox[n][j] : make_float4(0.f, 0.f, 0.f, 0.f);
    }
    __syncthreads();
    if (i >= MPROP || w >= NW) return;

    float4 b = g_sbox[n][i];
    float a1 = (b.z - b.x) * (b.w - b.y);
    unsigned bits = 0u;
#pragma unroll
    for (int jj = 0; jj < 32; jj++) {
        int j = w * 32 + jj;
        if (j < MPROP) {
            float4 c = jb[wloc * 32 + jj];
            float lx = fmaxf(b.x, c.x), ly = fmaxf(b.y, c.y);
            float rx = fminf(b.z, c.z), ry = fminf(b.w, c.w);
            float iw = fmaxf(rx - lx, 0.f), ih = fmaxf(ry - ly, 0.f);
            float inter = iw * ih;
            float a2 = (c.z - c.x) * (c.w - c.y);
            float iou = inter / fmaxf(a1 + a2 - inter, 1e-9f);
            if (iou > 0.7f) bits |= (1u << jj);
        }
    }
    g_mask[n][i][w] = bits;
}

// ---------------------------------------------------------------------------
// 5c) sequential scan with bitmask suppression
// ---------------------------------------------------------------------------
__global__ __launch_bounds__(192)
void scan_kernel(float* __restrict__ out) {
    __shared__ unsigned removed[NW];
    __shared__ float ssc[MPROP];
    const int n = blockIdx.x;
    const int t = threadIdx.x;

    for (int w = t; w < NW; w += 192) removed[w] = 0u;
    for (int i = t; i < MPROP; i += 192) ssc[i] = g_sscore[n][i];
    __syncthreads();

    int k = 0;
    for (int i = 0; i < MPROP; i++) {
        float sc = ssc[i];
        if (!(sc > -5e8f)) break;
        unsigned bit = (removed[i >> 5] >> (i & 31)) & 1u;
        if (!bit) {
            if (t == 0) {
                float4 b = g_sbox[n][i];
                float* o = out + ((size_t)n * POSTK + k) * 5;
                o[0] = b.x; o[1] = b.y; o[2] = b.z; o[3] = b.w; o[4] = sc;
            }
            const unsigned* mrow = g_mask[n][i];
            for (int w = t; w < NW; w += 192) removed[w] |= mrow[w];
            __syncthreads();
            k++;
            if (k == POSTK) break;
        }
    }
    for (int r = k + t; r < POSTK; r += 192) {
        float* o = out + ((size_t)n * POSTK + r) * 5;
        o[0] = 0.f; o[1] = 0.f; o[2] = 0.f; o[3] = 0.f; o[4] = NEG_INF;
    }
}

// ---------------------------------------------------------------------------
// launch
// ---------------------------------------------------------------------------
extern "C" void kernel_launch(void* const* d_in, const int* in_sizes, int n_in,
                              void* d_out, int out_size) {
    const float* feats[5];
    for (int i = 0; i < 5; i++) feats[i] = (const float*)d_in[i];
    const float* conv_w  = (const float*)d_in[5];
    const float* conv_b  = (const float*)d_in[6];
    const float* obj_w   = (const float*)d_in[7];
    const float* obj_b   = (const float*)d_in[8];
    const float* delta_w = (const float*)d_in[9];
    const float* delta_b = (const float*)d_in[10];
    float* out = (float*)d_out;

    cudaFuncSetAttribute(conv_mma_kernel, cudaFuncAttributeMaxDynamicSharedMemorySize, CMMA_SMEM);
    cudaFuncSetAttribute(sort_kernel, cudaFuncAttributeMaxDynamicSharedMemorySize, NSORT * 8);

    split_w_kernel<<<256, 256>>>(conv_w);
    {
        dim3 grid(1267, 4, NIMG);
        split_feat_kernel<<<grid, 256>>>(feats[0], feats[1], feats[2], feats[3], feats[4]);
    }
    {
        dim3 grid(634, 2, NIMG);
        conv_mma_kernel<<<grid, 256, CMMA_SMEM>>>(conv_b);
    }
    {
        dim3 grid(634, NIMG);
        head1x1_kernel<<<grid, 128>>>(obj_w, obj_b, delta_w, delta_b);
    }
    topk_kernel<<<10, 512>>>();
    decode_kernel<<<(NIMG * MPROP + 255) / 256, 256>>>();

    sort_kernel<<<NIMG, 1024, NSORT * 8>>>();
    {
        dim3 grid((MPROP + 127) / 128, (NW + 3) / 4, NIMG);
        mask_kernel<<<grid, 512>>>();
    }
    scan_kernel<<<NIMG, 192>>>(out);
}

// round 16
// speedup vs baseline: 1.7459x; 1.1228x over previous
#include <cuda_runtime.h>
#include <cuda_bf16.h>
#include <cuda_fp16.h>
#include <math.h>
#include <stdint.h>

#define NIMG 2
#define MALL 242991
#define MPOS 80997
#define MPROP 4741
#define POSTK 1000
#define NEG_INF (-1e9f)
#define NW 149
#define NWP 152                 // padded mask row (16B multiple)
#define NSORT 8192
#define CAND 16384
#define RSCALE 4096.0f
#define RINV   2.44140625e-4f   // 1/4096 exact

__constant__ int c_H[5]      = {200, 100, 50, 25, 13};
__constant__ int c_W[5]      = {304, 152, 76, 38, 19};
__constant__ int c_stride[5] = {4, 8, 16, 32, 64};
__constant__ int c_size[5]   = {32, 64, 128, 256, 512};
__constant__ int c_hw[5]     = {60800, 15200, 3800, 950, 247};
__constant__ int c_hwa[5]    = {182400, 45600, 11400, 2850, 741};
__constant__ int c_abase[5]  = {0, 182400, 228000, 239400, 242250};
__constant__ int c_pbase[5]  = {0, 60800, 76000, 79800, 80750};
__constant__ int c_k[5]      = {1000, 1000, 1000, 1000, 741};
__constant__ int c_sbase[5]  = {0, 1000, 2000, 3000, 4000};
__constant__ int c_tstart[6] = {0, 475, 594, 624, 632, 634};     // ceil(hw/128) cum
__constant__ int c_ft[6]     = {0, 950, 1188, 1248, 1263, 1267}; // ceil(hw/64) cum

// ---------------------------------------------------------------------------
// Device scratch (16B-aligned where cp.async touches them)
// ---------------------------------------------------------------------------
__device__ __align__(16) __half g_spA[2][(size_t)NIMG * MPOS * 256];
__device__ __align__(16) __half g_spB[2][256 * 2304];
__device__ __align__(16) float  g_t[(size_t)NIMG * MPOS * 256];
__device__ float  g_logits[NIMG * MALL];
__device__ float  g_deltas[(size_t)NIMG * MALL * 4];
__device__ int    g_topk[10][1024];
__device__ float4 g_pbox[NIMG][MPROP];
__device__ float  g_pscore[NIMG][MPROP];
__device__ float4 g_sbox[NIMG][MPROP];
__device__ float  g_sscore[NIMG][MPROP];
__device__ __align__(16) unsigned g_mask[NIMG][MPROP][NWP];

// ---------------------------------------------------------------------------
// helpers (sm_80-era PTX only)
// ---------------------------------------------------------------------------
__device__ __forceinline__ uint32_t smem_u32(const void* p) {
    uint32_t a;
    asm("{ .reg .u64 t; cvta.to.shared.u64 t, %1; cvt.u32.u64 %0, t; }" : "=r"(a) : "l"(p));
    return a;
}
__device__ __forceinline__ void cp_async16(uint32_t dst, const void* src, unsigned srcsz) {
    asm volatile("cp.async.ca.shared.global [%0], [%1], 16, %2;"
                 :: "r"(dst), "l"(src), "r"(srcsz) : "memory");
}
#define CP_COMMIT() asm volatile("cp.async.commit_group;" ::: "memory")
#define CP_WAIT0()  asm volatile("cp.async.wait_group 0;" ::: "memory")

__device__ __forceinline__ void ldsm4(uint32_t* r, uint32_t addr) {
    asm volatile("ldmatrix.sync.aligned.m8n8.x4.shared.b16 {%0,%1,%2,%3}, [%4];"
                 : "=r"(r[0]), "=r"(r[1]), "=r"(r[2]), "=r"(r[3]) : "r"(addr));
}
// fp16 mma, fp32 accum. In-TC chain (RZ) — used only WITHIN a windowed chunk.
__device__ __forceinline__ void mma_f16(float* c, const uint32_t* a, uint32_t b0, uint32_t b1) {
    asm volatile("mma.sync.aligned.m16n8k16.row.col.f32.f16.f16.f32 "
                 "{%0,%1,%2,%3}, {%4,%5,%6,%7}, {%8,%9}, {%0,%1,%2,%3};"
                 : "+f"(c[0]), "+f"(c[1]), "+f"(c[2]), "+f"(c[3])
                 : "r"(a[0]), "r"(a[1]), "r"(a[2]), "r"(a[3]), "r"(b0), "r"(b1));
}
__device__ __forceinline__ void mma_f16_zero(float* d, const uint32_t* a, uint32_t b0, uint32_t b1) {
    asm volatile("mma.sync.aligned.m16n8k16.row.col.f32.f16.f16.f32 "
                 "{%0,%1,%2,%3}, {%4,%5,%6,%7}, {%8,%9}, {%10,%11,%12,%13};"
                 : "=f"(d[0]), "=f"(d[1]), "=f"(d[2]), "=f"(d[3])
                 : "r"(a[0]), "r"(a[1]), "r"(a[2]), "r"(a[3]), "r"(b0), "r"(b1),
                   "f"(0.f), "f"(0.f), "f"(0.f), "f"(0.f));
}

// fp16 2-split with scaled residual (avoids fp16 subnormals on small weights)
__device__ __forceinline__ void split2(float x, __half& h, __half& r) {
    h = __float2half_rn(x);
    r = __float2half_rn((x - __half2float(h)) * RSCALE);
}

// ---------------------------------------------------------------------------
// 0a) split weights: cw[co][ci][tap] -> g_spB[q][co][tap*256+ci]
// ---------------------------------------------------------------------------
__global__ void split_w_kernel(const float* __restrict__ cw) {
    int co = blockIdx.x, t = threadIdx.x;
#pragma unroll
    for (int it = 0; it < 9; it++) {
        float v = cw[co * 2304 + t * 9 + it];
        __half h, r;
        split2(v, h, r);
        int k = co * 2304 + it * 256 + t;
        g_spB[0][k] = h; g_spB[1][k] = r;
    }
}

// ---------------------------------------------------------------------------
// 0b) split + transpose features: feat[n][ci][pos] -> g_spA[q][n*MPOS+pos][ci]
// ---------------------------------------------------------------------------
__global__ __launch_bounds__(256)
void split_feat_kernel(const float* __restrict__ f0, const float* __restrict__ f1,
                       const float* __restrict__ f2, const float* __restrict__ f3,
                       const float* __restrict__ f4) {
    __shared__ float sm[64][65];
    int tile = blockIdx.x;
    int l = 0;
    while (l < 4 && tile >= c_ft[l + 1]) l++;
    const float* feat = (l == 0) ? f0 : (l == 1) ? f1 : (l == 2) ? f2 : (l == 3) ? f3 : f4;
    int hw = c_hw[l], pB = c_pbase[l];
    int p0 = (tile - c_ft[l]) * 64;
    int ci0 = blockIdx.y * 64;
    int n = blockIdx.z;
    int t = threadIdx.x;

    {
        int ci = t >> 2, v0 = t & 3;
        const float* src = feat + ((size_t)(n * 256 + ci0 + ci)) * hw;
        int s0 = v0 * 16;
#pragma unroll
        for (int j = 0; j < 16; j++) {
            int p = p0 + s0 + j;
            sm[ci][s0 + j] = (p < hw) ? src[p] : 0.f;
        }
    }
    __syncthreads();
    {
        int pos = t >> 2, g = t & 3;
        if (p0 + pos < hw) {
            union { __half h[16]; uint4 v[2]; } bh, br;
#pragma unroll
            for (int e = 0; e < 16; e++)
                split2(sm[g * 16 + e][pos], bh.h[e], br.h[e]);
            size_t drow = ((size_t)(n * MPOS + pB + p0 + pos)) * 256 + ci0 + g * 16;
            *(uint4*)(&g_spA[0][drow]) = bh.v[0]; *(uint4*)(&g_spA[0][drow + 8]) = bh.v[1];
            *(uint4*)(&g_spA[1][drow]) = br.v[0]; *(uint4*)(&g_spA[1][drow + 8]) = br.v[1];
        }
    }
}

// ---------------------------------------------------------------------------
// 1) conv3x3 as implicit GEMM on mma.sync (fp16 2-split scaled, 3 terms)
// ---------------------------------------------------------------------------
#define TILE_B 18432                 // 128 rows * 144 B
#define STAGE_BYTES (4 * TILE_B)     // 73728
#define CMMA_SMEM (1024 + 2 * STAGE_BYTES)   // 148480

struct GatherCtx {
    int n, pB, W, H, hw, flat, xx, yy, su, r;
    size_t browB;
};

__device__ __forceinline__ void prefetch_chunk(const GatherCtx& g, int c, uint32_t sbase) {
    const int tap = c >> 2, ci0 = (c & 3) * 64;
    const int dy = tap / 3 - 1, dx = tap % 3 - 1;
    const int k0 = tap * 256 + ci0;

    const int xs = g.xx + dx, ys = g.yy + dy;
    const bool valid = (g.flat < g.hw) && (xs >= 0) && (xs < g.W) && (ys >= 0) && (ys < g.H);
    const unsigned srcsz = valid ? 16u : 0u;
    const size_t srow = valid
        ? (((size_t)(g.n * MPOS + g.pB + g.flat + dy * g.W + dx)) * 256 + ci0) : (size_t)0;

    const uint32_t rowoff = (uint32_t)(g.r * 144);
#pragma unroll
    for (int q = 0; q < 2; q++) {
        const __half* gp = &g_spA[q][srow];
        const uint32_t db = sbase + q * TILE_B + rowoff;
#pragma unroll
        for (int v = 0; v < 4; v++) {
            int vec = g.su * 4 + v;
            cp_async16(db + vec * 16, gp + vec * 8, srcsz);
        }
    }
    const size_t br = g.browB + k0;
#pragma unroll
    for (int q = 0; q < 2; q++) {
        const __half* gp = &g_spB[q][br];
        const uint32_t db = sbase + (2 + q) * TILE_B + rowoff;
#pragma unroll
        for (int v = 0; v < 4; v++) {
            int vec = g.su * 4 + v;
            cp_async16(db + vec * 16, gp + vec * 8, 16u);
        }
    }
}

__global__ __launch_bounds__(256, 1)
void conv_mma_kernel(const float* __restrict__ cb) {
    extern __shared__ char smem[];
    const uint32_t sb = smem_u32(smem);
    const int tid = threadIdx.x;
    const int lane = tid & 31;
    const int wid = tid >> 5;
    const int mbase = (wid & 3) * 32;
    const int nbase = (wid >> 2) * 64;

    const int tile = blockIdx.x;
    const int half = blockIdx.y;
    const int n    = blockIdx.z;
    int l = 0;
    while (l < 4 && tile >= c_tstart[l + 1]) l++;
    const int H = c_H[l], W = c_W[l], hw = c_hw[l], pB = c_pbase[l];
    const int base = (tile - c_tstart[l]) * 128;
    const int ch0 = half * 128;

    if (tid < 128) ((float*)smem)[tid] = cb[ch0 + tid];

    GatherCtx g;
    g.n = n; g.pB = pB; g.W = W; g.H = H; g.hw = hw;
    g.r = tid >> 1; g.su = tid & 1;
    g.flat = base + g.r;
    g.yy = (g.flat < hw) ? (g.flat / W) : 0;
    g.xx = g.flat - g.yy * W;
    g.browB = ((size_t)(ch0 + g.r)) * 2304;

    float acc[2][8][4];
#pragma unroll
    for (int i = 0; i < 2; i++)
#pragma unroll
        for (int j = 0; j < 8; j++)
#pragma unroll
            for (int k = 0; k < 4; k++) acc[i][j][k] = 0.f;

    const int rowA0 = mbase + (lane & 7) + (lane & 8);
    const int colA  = ((lane >> 4) & 1) * 16;
    const int rowB0 = nbase + (lane & 7) + ((lane >> 1) & 8);
    const int colB  = ((lane >> 3) & 1) * 16;

    prefetch_chunk(g, 0, sb + 1024);
    CP_COMMIT();

#pragma unroll 1
    for (int c = 0; c < 36; c++) {
        const int st = c & 1;
        CP_WAIT0();
        __syncthreads();
        if (c + 1 < 36) {
            prefetch_chunk(g, c + 1, sb + 1024 + (st ^ 1) * STAGE_BYTES);
            CP_COMMIT();
        }
        const uint32_t sbase = sb + 1024 + st * STAGE_BYTES;
        const uint32_t Ah = sbase, Ar = sbase + TILE_B;
        const uint32_t Bh = sbase + 2 * TILE_B, Br = sbase + 3 * TILE_B;

        // ---- window 1: hh ----
        {
            float tmp[2][8][4];
#pragma unroll
            for (int ks = 0; ks < 4; ks++) {
                uint32_t afr[2][4];
#pragma unroll
                for (int mt = 0; mt < 2; mt++) {
                    int row = rowA0 + mt * 16;
                    ldsm4(afr[mt], Ah + row * 144 + ks * 32 + colA);
                }
#pragma unroll
                for (int t = 0; t < 4; t++) {
                    uint32_t bfr[4];
                    int row = rowB0 + t * 16;
                    ldsm4(bfr, Bh + row * 144 + ks * 32 + colB);
#pragma unroll
                    for (int mt = 0; mt < 2; mt++) {
                        if (ks == 0) {
                            mma_f16_zero(tmp[mt][t * 2],     afr[mt], bfr[0], bfr[1]);
                            mma_f16_zero(tmp[mt][t * 2 + 1], afr[mt], bfr[2], bfr[3]);
                        } else {
                            mma_f16(tmp[mt][t * 2],     afr[mt], bfr[0], bfr[1]);
                            mma_f16(tmp[mt][t * 2 + 1], afr[mt], bfr[2], bfr[3]);
                        }
                    }
                }
            }
#pragma unroll
            for (int mt = 0; mt < 2; mt++)
#pragma unroll
                for (int j = 0; j < 8; j++)
#pragma unroll
                    for (int kk = 0; kk < 4; kk++)
                        acc[mt][j][kk] += tmp[mt][j][kk];
        }

        // ---- window 2: h*r' + r'*h (scaled by 2^12), one shared chain ----
        {
            float tmp[2][8][4];
#pragma unroll
            for (int ks = 0; ks < 4; ks++) {
                uint32_t ah[2][4], ar[2][4];
#pragma unroll
                for (int mt = 0; mt < 2; mt++) {
                    int row = rowA0 + mt * 16;
                    ldsm4(ah[mt], Ah + row * 144 + ks * 32 + colA);
                    ldsm4(ar[mt], Ar + row * 144 + ks * 32 + colA);
                }
#pragma unroll
                for (int t = 0; t < 4; t++) {
                    uint32_t bh[4], br[4];
                    int row = rowB0 + t * 16;
                    ldsm4(bh, Bh + row * 144 + ks * 32 + colB);
                    ldsm4(br, Br + row * 144 + ks * 32 + colB);
#pragma unroll
                    for (int mt = 0; mt < 2; mt++) {
                        if (ks == 0) {
                            mma_f16_zero(tmp[mt][t * 2],     ah[mt], br[0], br[1]);
                            mma_f16_zero(tmp[mt][t * 2 + 1], ah[mt], br[2], br[3]);
                        } else {
                            mma_f16(tmp[mt][t * 2],     ah[mt], br[0], br[1]);
                            mma_f16(tmp[mt][t * 2 + 1], ah[mt], br[2], br[3]);
                        }
                        mma_f16(tmp[mt][t * 2],     ar[mt], bh[0], bh[1]);
                        mma_f16(tmp[mt][t * 2 + 1], ar[mt], bh[2], bh[3]);
                    }
                }
            }
#pragma unroll
            for (int mt = 0; mt < 2; mt++)
#pragma unroll
                for (int j = 0; j < 8; j++)
#pragma unroll
                    for (int kk = 0; kk < 4; kk++)
                        acc[mt][j][kk] = fmaf(tmp[mt][j][kk], RINV, acc[mt][j][kk]);
        }
    }

    // epilogue: bias + relu, write g_t[pos][c]
    const float* bias = (const float*)smem;
#pragma unroll
    for (int mt = 0; mt < 2; mt++) {
#pragma unroll
        for (int nt = 0; nt < 8; nt++) {
            int nn = nbase + nt * 8 + (lane & 3) * 2;
            float bn0 = bias[nn], bn1 = bias[nn + 1];
#pragma unroll
            for (int h2 = 0; h2 < 2; h2++) {
                int m = mbase + mt * 16 + (lane >> 2) + h2 * 8;
                int fl = base + m;
                if (fl < hw) {
                    float v0 = fmaxf(acc[mt][nt][h2 * 2 + 0] + bn0, 0.f);
                    float v1 = fmaxf(acc[mt][nt][h2 * 2 + 1] + bn1, 0.f);
                    *(float2*)&g_t[((size_t)(n * MPOS + pB + fl)) * 256 + ch0 + nn] =
                        make_float2(v0, v1);
                }
            }
        }
    }
}

// ---------------------------------------------------------------------------
// 2) 1x1 heads — merged single launch over all levels (128-pos tiles)
// ---------------------------------------------------------------------------
__global__ void head1x1_kernel(const float* __restrict__ ow, const float* __restrict__ ob,
                               const float* __restrict__ dw, const float* __restrict__ db) {
    __shared__ float w2[15 * 256];
    __shared__ float b2[15];
    const int t = threadIdx.x;
    for (int i = t; i < 3 * 256; i += 128) w2[i] = ow[i];
    for (int i = t; i < 12 * 256; i += 128) w2[768 + i] = dw[i];
    if (t < 3) b2[t] = ob[t];
    else if (t < 15) b2[t] = db[t - 3];
    __syncthreads();

    const int tile = blockIdx.x;
    const int n    = blockIdx.y;
    int l = 0;
    while (l < 4 && tile >= c_tstart[l + 1]) l++;
    const int hw = c_hw[l], pB = c_pbase[l], aB = c_abase[l];
    const int pos = (tile - c_tstart[l]) * 128 + t;
    if (pos >= hw) return;

    const float4* trow = (const float4*)(g_t + ((size_t)(n * MPOS + pB + pos)) * 256);
    float acc[15];
#pragma unroll
    for (int o = 0; o < 15; o++) acc[o] = 0.f;

#pragma unroll 4
    for (int c4 = 0; c4 < 64; c4++) {
        float4 tv = trow[c4];
#pragma unroll
        for (int o = 0; o < 15; o++) {
            const float* wr = &w2[o * 256 + c4 * 4];
            acc[o] += tv.x * wr[0] + tv.y * wr[1] + tv.z * wr[2] + tv.w * wr[3];
        }
    }
    size_t ob_ = (size_t)n * MALL;
    int m = aB + pos * 3;
#pragma unroll
    for (int a = 0; a < 3; a++) {
        g_logits[ob_ + m + a] = acc[a] + b2[a];
#pragma unroll
        for (int d = 0; d < 4; d++)
            g_deltas[(ob_ + m + a) * 4 + d] = acc[3 + a * 4 + d] + b2[3 + a * 4 + d];
    }
}

// ---------------------------------------------------------------------------
// 3) exact top-k: histogram pass + candidate compaction + smem bitonic sort
// ---------------------------------------------------------------------------
__device__ __forceinline__ unsigned flipf(float f) {
    unsigned u = __float_as_uint(f);
    return (u & 0x80000000u) ? ~u : (u | 0x80000000u);
}

__global__ __launch_bounds__(512)
void topk_kernel() {
    extern __shared__ unsigned long long cand[];   // [CAND]
    __shared__ unsigned hist[2048];
    __shared__ unsigned sB1;
    __shared__ int sCnt;

    const int blk = blockIdx.x;
    const int n = blk / 5, l = blk % 5;
    const int NE = c_hwa[l];
    const int K  = c_k[l];
    const float* sc = g_logits + (size_t)n * MALL + c_abase[l];
    const int t = threadIdx.x;

    for (int i = t; i < 2048; i += 512) hist[i] = 0;
    __syncthreads();
    for (int i = t; i < NE; i += 512) atomicAdd(&hist[flipf(sc[i]) >> 21], 1u);
    __syncthreads();
    if (t == 0) {
        unsigned acc = 0; int b = 2047;
        for (; b >= 0; b--) { unsigned h = hist[b]; if (acc + h >= (unsigned)K) break; acc += h; }
        sB1 = (unsigned)b;
        sCnt = 0;
    }
    __syncthreads();
    const unsigned B1 = sB1;

    for (int i = t; i < NE; i += 512) {
        unsigned k = flipf(sc[i]);
        if ((k >> 21) >= B1) {
            int s = atomicAdd(&sCnt, 1);
            if (s < CAND)
                cand[s] = ((unsigned long long)k << 32) | (unsigned)(~(unsigned)i);
        }
    }
    __syncthreads();
    int C = sCnt < CAND ? sCnt : CAND;
    int nsort = 1024;
    while (nsort < C) nsort <<= 1;
    for (int i = C + t; i < nsort; i += 512) cand[i] = 0ull;
    __syncthreads();

    for (unsigned k2 = 2; k2 <= (unsigned)nsort; k2 <<= 1) {
        for (unsigned j = k2 >> 1; j > 0; j >>= 1) {
            __syncthreads();
            for (unsigned i = t; i < (unsigned)nsort; i += 512) {
                unsigned ixj = i ^ j;
                if (ixj > i) {
                    bool dir = ((i & k2) == 0);
                    unsigned long long a = cand[i], b = cand[ixj];
                    if ((a < b) == dir) { cand[i] = b; cand[ixj] = a; }
                }
            }
        }
    }
    __syncthreads();
    for (int s = t; s < K; s += 512)
        g_topk[blk][s] = (int)(~(unsigned)(cand[s] & 0xFFFFFFFFull));
}

// ---------------------------------------------------------------------------
// 4) decode
// ---------------------------------------------------------------------------
__global__ void decode_kernel() {
    int sid = blockIdx.x * 256 + threadIdx.x;
    if (sid >= NIMG * MPROP) return;
    int n = sid / MPROP, s = sid - n * MPROP;
    int l = s / 1000; if (l > 4) l = 4;
    int kl = s - c_sbase[l];
    int blk = n * 5 + l;
    int idx = g_topk[blk][kl];

    float score = g_logits[(size_t)n * MALL + c_abase[l] + idx];
    int pos = idx / 3, a = idx - pos * 3;
    int W = c_W[l];
    int yy = pos / W, xx = pos - yy * W;

    double size = (double)c_size[l];
    double ratio = (a == 0) ? 0.5 : ((a == 1) ? 1.0 : 2.0);
    double wd = sqrt(size * size / ratio);
    double hd = wd * ratio;

    float sx = (float)(xx * c_stride[l]);
    float sy = (float)(yy * c_stride[l]);
    float ax1 = sx + (float)(-wd * 0.5), ay1 = sy + (float)(-hd * 0.5);
    float ax2 = sx + (float)(wd * 0.5),  ay2 = sy + (float)(hd * 0.5);

    float w = ax2 - ax1, h = ay2 - ay1;
    float cx = ax1 + 0.5f * w, cy = ay1 + 0.5f * h;

    const float* dp = &g_deltas[((size_t)n * MALL + c_abase[l] + idx) * 4];
    const float CLAMP = (float)4.135166556742356;
    float dwv = fminf(dp[2], CLAMP);
    float dhv = fminf(dp[3], CLAMP);

    float pcx = dp[0] * w + cx, pcy = dp[1] * h + cy;
    float pw = expf(dwv) * w, ph = expf(dhv) * h;

    float x1 = pcx - 0.5f * pw, y1 = pcy - 0.5f * ph;
    float x2 = pcx + 0.5f * pw, y2 = pcy + 0.5f * ph;
    x1 = fminf(fmaxf(x1, 0.f), 1216.f);
    x2 = fminf(fmaxf(x2, 0.f), 1216.f);
    y1 = fminf(fmaxf(y1, 0.f), 800.f);
    y2 = fminf(fmaxf(y2, 0.f), 800.f);

    bool valid = ((x2 - x1) > 0.f) && ((y2 - y1) > 0.f);
    g_pbox[n][s] = make_float4(x1, y1, x2, y2);
    g_pscore[n][s] = valid ? score : NEG_INF;
}

// ---------------------------------------------------------------------------
// 5a) sort pooled proposals by (score desc, idx asc)
// ---------------------------------------------------------------------------
__global__ __launch_bounds__(1024)
void sort_kernel() {
    extern __shared__ unsigned long long sbuf[];
    const int n = blockIdx.x;
    const int t = threadIdx.x;

    for (int i = t; i < NSORT; i += 1024) {
        unsigned long long key = 0ull;
        if (i < MPROP) {
            float s = g_pscore[n][i];
            key = ((unsigned long long)flipf(s) << 32) | (unsigned)(~(unsigned)i);
        }
        sbuf[i] = key;
    }
    for (unsigned k2 = 2; k2 <= NSORT; k2 <<= 1) {
        for (unsigned j = k2 >> 1; j > 0; j >>= 1) {
            __syncthreads();
            for (unsigned i = t; i < NSORT; i += 1024) {
                unsigned ixj = i ^ j;
                if (ixj > i) {
                    bool dir = ((i & k2) == 0);
                    unsigned long long a = sbuf[i], b = sbuf[ixj];
                    if ((a < b) == dir) { sbuf[i] = b; sbuf[ixj] = a; }
                }
            }
        }
    }
    __syncthreads();
    for (int r = t; r < MPROP; r += 1024) {
        unsigned idx = ~(unsigned)(sbuf[r] & 0xFFFFFFFFull);
        g_sbox[n][r]   = g_pbox[n][idx];
        g_sscore[n][r] = g_pscore[n][idx];
    }
}

// ---------------------------------------------------------------------------
// 5b) suppression bitmask (row padded to NWP words)
// ---------------------------------------------------------------------------
__global__ __launch_bounds__(512)
void mask_kernel() {
    __shared__ float4 jb[128];
    const int n = blockIdx.z;
    const int tid = threadIdx.x;
    const int i = blockIdx.x * 128 + (tid & 127);
    const int wloc = tid >> 7;
    const int w = blockIdx.y * 4 + wloc;
    const int j0 = blockIdx.y * 128;

    if (tid < 128) {
        int j = j0 + tid;
        jb[tid] = (j < MPROP) ? g_sbox[n][j] : make_float4(0.f, 0.f, 0.f, 0.f);
    }
    __syncthreads();
    if (i >= MPROP || w >= NWP) return;

    float4 b = g_sbox[n][i];
    float a1 = (b.z - b.x) * (b.w - b.y);
    unsigned bits = 0u;
#pragma unroll
    for (int jj = 0; jj < 32; jj++) {
        int j = w * 32 + jj;
        if (j < MPROP) {
            float4 c = jb[wloc * 32 + jj];
            float lx = fmaxf(b.x, c.x), ly = fmaxf(b.y, c.y);
            float rx = fminf(b.z, c.z), ry = fminf(b.w, c.w);
            float iw = fmaxf(rx - lx, 0.f), ih = fmaxf(ry - ly, 0.f);
            float inter = iw * ih;
            float a2 = (c.z - c.x) * (c.w - c.y);
            float iou = inter / fmaxf(a1 + a2 - inter, 1e-9f);
            if (iou > 0.7f) bits |= (1u << jj);
        }
    }
    g_mask[n][i][w] = bits;
}

// ---------------------------------------------------------------------------
// 5c) chunked scan: 32 candidates per chunk, double-buffered mask rows
//     dynamic smem layout: cm[2][32*NWP] (offset 0, 16B aligned) + ssc[MPROP]
// ---------------------------------------------------------------------------
#define CMBYTES (2 * 32 * NWP * 4)
#define SCAN_SMEM (CMBYTES + MPROP * 4)

__global__ __launch_bounds__(256)
void scan_kernel(float* __restrict__ out) {
    extern __shared__ char sm[];
    unsigned* cm  = (unsigned*)sm;                  // [2][32*NWP], offset 0 (16B aligned)
    float*    ssc = (float*)(sm + CMBYTES);         // [MPROP]
    __shared__ unsigned removed[NWP];
    __shared__ int selj[32];
    __shared__ int s_cnt;
    __shared__ unsigned s_selbits;
    __shared__ int s_vcnt;

    const int n = blockIdx.x;
    const int t = threadIdx.x;
    const uint32_t cm_s = smem_u32(cm);

    for (int i = t; i < MPROP; i += 256) ssc[i] = g_sscore[n][i];
    for (int w = t; w < NWP; w += 256) removed[w] = 0u;
    if (t == 0) s_vcnt = 0;
    __syncthreads();
    {
        int cnt = 0;
        for (int i = t; i < MPROP; i += 256)
            if (ssc[i] > -5e8f) cnt++;
        if (cnt) atomicAdd(&s_vcnt, cnt);
    }
    __syncthreads();
    const int vlimit = s_vcnt;
    const int nchunks = (vlimit + 31) >> 5;

    // prefetch chunk 0
    if (nchunks > 0) {
        int rows = (32 < MPROP) ? 32 : MPROP;
        for (int idx = t; idx < rows * (NWP / 4); idx += 256) {
            int rr = idx / (NWP / 4), u = idx % (NWP / 4);
            cp_async16(cm_s + (rr * NWP + u * 4) * 4, &g_mask[n][rr][u * 4], 16u);
        }
        CP_COMMIT();
    }

    int k = 0;
    for (int c = 0; c < nchunks && k < POSTK; c++) {
        CP_WAIT0();
        __syncthreads();
        const int buf = c & 1;
        // prefetch next chunk
        if (c + 1 < nchunks) {
            int j0n = (c + 1) * 32;
            int rows = MPROP - j0n; if (rows > 32) rows = 32;
            uint32_t db = cm_s + ((c + 1) & 1) * 32 * NWP * 4;
            for (int idx = t; idx < rows * (NWP / 4); idx += 256) {
                int rr = idx / (NWP / 4), u = idx % (NWP / 4);
                cp_async16(db + (rr * NWP + u * 4) * 4, &g_mask[n][j0n + rr][u * 4], 16u);
            }
            CP_COMMIT();
        }
        const int j0 = c * 32;
        const int nc = (vlimit - j0 < 32) ? (vlimit - j0) : 32;
        const unsigned* cmb = cm + buf * 32 * NWP;

        if (t == 0) {
            unsigned lrm = removed[c];      // word c == boxes j0..j0+31
            unsigned selbits = 0;
            int cnt = 0;
            for (int kk = 0; kk < nc; kk++) {
                if (!((lrm >> kk) & 1u)) {
                    selbits |= 1u << kk;
                    selj[cnt++] = j0 + kk;
                    lrm |= cmb[kk * NWP + c];
                    if (k + cnt == POSTK) break;
                }
            }
            s_selbits = selbits;
            s_cnt = cnt;
        }
        __syncthreads();
        const unsigned selbits = s_selbits;
        const int cnt = s_cnt;
        if (selbits) {
            for (int w = t; w < NWP; w += 256) {
                unsigned orv = removed[w];
                unsigned sb = selbits;
                while (sb) {
                    int kk = __ffs(sb) - 1;
                    sb &= sb - 1;
                    orv |= cmb[kk * NWP + w];
                }
                removed[w] = orv;
            }
            if (t < cnt) {
                int j = selj[t];
                float4 b = g_sbox[n][j];
                float* o = out + ((size_t)n * POSTK + k + t) * 5;
                o[0] = b.x; o[1] = b.y; o[2] = b.z; o[3] = b.w; o[4] = ssc[j];
            }
        }
        k += cnt;
        __syncthreads();
    }
    for (int r = k + t; r < POSTK; r += 256) {
        float* o = out + ((size_t)n * POSTK + r) * 5;
        o[0] = 0.f; o[1] = 0.f; o[2] = 0.f; o[3] = 0.f; o[4] = NEG_INF;
    }
}

// ---------------------------------------------------------------------------
// launch
// ---------------------------------------------------------------------------
extern "C" void kernel_launch(void* const* d_in, const int* in_sizes, int n_in,
                              void* d_out, int out_size) {
    const float* feats[5];
    for (int i = 0; i < 5; i++) feats[i] = (const float*)d_in[i];
    const float* conv_w  = (const float*)d_in[5];
    const float* conv_b  = (const float*)d_in[6];
    const float* obj_w   = (const float*)d_in[7];
    const float* obj_b   = (const float*)d_in[8];
    const float* delta_w = (const float*)d_in[9];
    const float* delta_b = (const float*)d_in[10];
    float* out = (float*)d_out;

    cudaFuncSetAttribute(conv_mma_kernel, cudaFuncAttributeMaxDynamicSharedMemorySize, CMMA_SMEM);
    cudaFuncSetAttribute(sort_kernel, cudaFuncAttributeMaxDynamicSharedMemorySize, NSORT * 8);
    cudaFuncSetAttribute(topk_kernel, cudaFuncAttributeMaxDynamicSharedMemorySize, CAND * 8);
    cudaFuncSetAttribute(scan_kernel, cudaFuncAttributeMaxDynamicSharedMemorySize, SCAN_SMEM);

    split_w_kernel<<<256, 256>>>(conv_w);
    {
        dim3 grid(1267, 4, NIMG);
        split_feat_kernel<<<grid, 256>>>(feats[0], feats[1], feats[2], feats[3], feats[4]);
    }
    {
        dim3 grid(634, 2, NIMG);
        conv_mma_kernel<<<grid, 256, CMMA_SMEM>>>(conv_b);
    }
    {
        dim3 grid(634, NIMG);
        head1x1_kernel<<<grid, 128>>>(obj_w, obj_b, delta_w, delta_b);
    }
    topk_kernel<<<10, 512, CAND * 8>>>();
    decode_kernel<<<(NIMG * MPROP + 255) / 256, 256>>>();

    sort_kernel<<<NIMG, 1024, NSORT * 8>>>();
    {
        dim3 grid((MPROP + 127) / 128, (NWP + 3) / 4, NIMG);
        mask_kernel<<<grid, 512>>>();
    }
    scan_kernel<<<NIMG, 256, SCAN_SMEM>>>(out);
}

// round 17
// speedup vs baseline: 1.7465x; 1.0004x over previous
#include <cuda_runtime.h>
#include <cuda_bf16.h>
#include <cuda_fp16.h>
#include <math.h>
#include <stdint.h>

#define NIMG 2
#define MALL 242991
#define MPOS 80997
#define MPROP 4741
#define POSTK 1000
#define NEG_INF (-1e9f)
#define NW 149
#define NWP 152                 // padded mask row (16B multiple)
#define CAND 16384
#define RSCALE 4096.0f
#define RINV   2.44140625e-4f   // 1/4096 exact

__constant__ int c_H[5]      = {200, 100, 50, 25, 13};
__constant__ int c_W[5]      = {304, 152, 76, 38, 19};
__constant__ int c_stride[5] = {4, 8, 16, 32, 64};
__constant__ int c_size[5]   = {32, 64, 128, 256, 512};
__constant__ int c_hw[5]     = {60800, 15200, 3800, 950, 247};
__constant__ int c_hwa[5]    = {182400, 45600, 11400, 2850, 741};
__constant__ int c_abase[5]  = {0, 182400, 228000, 239400, 242250};
__constant__ int c_pbase[5]  = {0, 60800, 76000, 79800, 80750};
__constant__ int c_k[5]      = {1000, 1000, 1000, 1000, 741};
__constant__ int c_sbase[5]  = {0, 1000, 2000, 3000, 4000};
__constant__ int c_tstart[6] = {0, 475, 594, 624, 632, 634};     // ceil(hw/128) cum
__constant__ int c_ft[6]     = {0, 950, 1188, 1248, 1263, 1267}; // ceil(hw/64) cum

// ---------------------------------------------------------------------------
// Device scratch
// ---------------------------------------------------------------------------
__device__ __align__(16) __half g_spA[2][(size_t)NIMG * MPOS * 256];
__device__ __align__(16) __half g_spB[2][256 * 2304];
__device__ __align__(16) float  g_t[(size_t)NIMG * MPOS * 256];
__device__ float  g_logits[NIMG * MALL];
__device__ float  g_deltas[(size_t)NIMG * MALL * 4];
__device__ int    g_topk[10][1024];
__device__ float4 g_pbox[NIMG][MPROP];
__device__ float  g_pscore[NIMG][MPROP];
__device__ float4 g_sbox[NIMG][MPROP];
__device__ float  g_sscore[NIMG][MPROP];
__device__ __align__(16) unsigned g_mask[NIMG][MPROP][NWP];
__device__ unsigned long long g_vkey[NIMG][5][1024];
__device__ int    g_vpool[NIMG][5][1024];
__device__ int    g_vcnt[NIMG][5];

// ---------------------------------------------------------------------------
// helpers (sm_80-era PTX only)
// ---------------------------------------------------------------------------
__device__ __forceinline__ uint32_t smem_u32(const void* p) {
    uint32_t a;
    asm("{ .reg .u64 t; cvta.to.shared.u64 t, %1; cvt.u32.u64 %0, t; }" : "=r"(a) : "l"(p));
    return a;
}
__device__ __forceinline__ void cp_async16(uint32_t dst, const void* src, unsigned srcsz) {
    asm volatile("cp.async.ca.shared.global [%0], [%1], 16, %2;"
                 :: "r"(dst), "l"(src), "r"(srcsz) : "memory");
}
#define CP_COMMIT() asm volatile("cp.async.commit_group;" ::: "memory")
#define CP_WAIT0()  asm volatile("cp.async.wait_group 0;" ::: "memory")

__device__ __forceinline__ void ldsm4(uint32_t* r, uint32_t addr) {
    asm volatile("ldmatrix.sync.aligned.m8n8.x4.shared.b16 {%0,%1,%2,%3}, [%4];"
                 : "=r"(r[0]), "=r"(r[1]), "=r"(r[2]), "=r"(r[3]) : "r"(addr));
}
__device__ __forceinline__ void mma_f16(float* c, const uint32_t* a, uint32_t b0, uint32_t b1) {
    asm volatile("mma.sync.aligned.m16n8k16.row.col.f32.f16.f16.f32 "
                 "{%0,%1,%2,%3}, {%4,%5,%6,%7}, {%8,%9}, {%0,%1,%2,%3};"
                 : "+f"(c[0]), "+f"(c[1]), "+f"(c[2]), "+f"(c[3])
                 : "r"(a[0]), "r"(a[1]), "r"(a[2]), "r"(a[3]), "r"(b0), "r"(b1));
}
__device__ __forceinline__ void mma_f16_zero(float* d, const uint32_t* a, uint32_t b0, uint32_t b1) {
    asm volatile("mma.sync.aligned.m16n8k16.row.col.f32.f16.f16.f32 "
                 "{%0,%1,%2,%3}, {%4,%5,%6,%7}, {%8,%9}, {%10,%11,%12,%13};"
                 : "=f"(d[0]), "=f"(d[1]), "=f"(d[2]), "=f"(d[3])
                 : "r"(a[0]), "r"(a[1]), "r"(a[2]), "r"(a[3]), "r"(b0), "r"(b1),
                   "f"(0.f), "f"(0.f), "f"(0.f), "f"(0.f));
}

__device__ __forceinline__ void split2(float x, __half& h, __half& r) {
    h = __float2half_rn(x);
    r = __float2half_rn((x - __half2float(h)) * RSCALE);
}

// ---------------------------------------------------------------------------
// 0a) split weights
// ---------------------------------------------------------------------------
__global__ void split_w_kernel(const float* __restrict__ cw) {
    int co = blockIdx.x, t = threadIdx.x;
#pragma unroll
    for (int it = 0; it < 9; it++) {
        float v = cw[co * 2304 + t * 9 + it];
        __half h, r;
        split2(v, h, r);
        int k = co * 2304 + it * 256 + t;
        g_spB[0][k] = h; g_spB[1][k] = r;
    }
}

// ---------------------------------------------------------------------------
// 0b) split + transpose features
// ---------------------------------------------------------------------------
__global__ __launch_bounds__(256)
void split_feat_kernel(const float* __restrict__ f0, const float* __restrict__ f1,
                       const float* __restrict__ f2, const float* __restrict__ f3,
                       const float* __restrict__ f4) {
    __shared__ float sm[64][65];
    int tile = blockIdx.x;
    int l = 0;
    while (l < 4 && tile >= c_ft[l + 1]) l++;
    const float* feat = (l == 0) ? f0 : (l == 1) ? f1 : (l == 2) ? f2 : (l == 3) ? f3 : f4;
    int hw = c_hw[l], pB = c_pbase[l];
    int p0 = (tile - c_ft[l]) * 64;
    int ci0 = blockIdx.y * 64;
    int n = blockIdx.z;
    int t = threadIdx.x;

    {
        int ci = t >> 2, v0 = t & 3;
        const float* src = feat + ((size_t)(n * 256 + ci0 + ci)) * hw;
        int s0 = v0 * 16;
#pragma unroll
        for (int j = 0; j < 16; j++) {
            int p = p0 + s0 + j;
            sm[ci][s0 + j] = (p < hw) ? src[p] : 0.f;
        }
    }
    __syncthreads();
    {
        int pos = t >> 2, g = t & 3;
        if (p0 + pos < hw) {
            union { __half h[16]; uint4 v[2]; } bh, br;
#pragma unroll
            for (int e = 0; e < 16; e++)
                split2(sm[g * 16 + e][pos], bh.h[e], br.h[e]);
            size_t drow = ((size_t)(n * MPOS + pB + p0 + pos)) * 256 + ci0 + g * 16;
            *(uint4*)(&g_spA[0][drow]) = bh.v[0]; *(uint4*)(&g_spA[0][drow + 8]) = bh.v[1];
            *(uint4*)(&g_spA[1][drow]) = br.v[0]; *(uint4*)(&g_spA[1][drow + 8]) = br.v[1];
        }
    }
}

// ---------------------------------------------------------------------------
// 1) conv3x3 as implicit GEMM on mma.sync (fp16 2-split scaled, 3 terms)
// ---------------------------------------------------------------------------
#define TILE_B 18432
#define STAGE_BYTES (4 * TILE_B)
#define CMMA_SMEM (1024 + 2 * STAGE_BYTES)

struct GatherCtx {
    int n, pB, W, H, hw, flat, xx, yy, su, r;
    size_t browB;
};

__device__ __forceinline__ void prefetch_chunk(const GatherCtx& g, int c, uint32_t sbase) {
    const int tap = c >> 2, ci0 = (c & 3) * 64;
    const int dy = tap / 3 - 1, dx = tap % 3 - 1;
    const int k0 = tap * 256 + ci0;

    const int xs = g.xx + dx, ys = g.yy + dy;
    const bool valid = (g.flat < g.hw) && (xs >= 0) && (xs < g.W) && (ys >= 0) && (ys < g.H);
    const unsigned srcsz = valid ? 16u : 0u;
    const size_t srow = valid
        ? (((size_t)(g.n * MPOS + g.pB + g.flat + dy * g.W + dx)) * 256 + ci0) : (size_t)0;

    const uint32_t rowoff = (uint32_t)(g.r * 144);
#pragma unroll
    for (int q = 0; q < 2; q++) {
        const __half* gp = &g_spA[q][srow];
        const uint32_t db = sbase + q * TILE_B + rowoff;
#pragma unroll
        for (int v = 0; v < 4; v++) {
            int vec = g.su * 4 + v;
            cp_async16(db + vec * 16, gp + vec * 8, srcsz);
        }
    }
    const size_t br = g.browB + k0;
#pragma unroll
    for (int q = 0; q < 2; q++) {
        const __half* gp = &g_spB[q][br];
        const uint32_t db = sbase + (2 + q) * TILE_B + rowoff;
#pragma unroll
        for (int v = 0; v < 4; v++) {
            int vec = g.su * 4 + v;
            cp_async16(db + vec * 16, gp + vec * 8, 16u);
        }
    }
}

__global__ __launch_bounds__(256, 1)
void conv_mma_kernel(const float* __restrict__ cb) {
    extern __shared__ char smem[];
    const uint32_t sb = smem_u32(smem);
    const int tid = threadIdx.x;
    const int lane = tid & 31;
    const int wid = tid >> 5;
    const int mbase = (wid & 3) * 32;
    const int nbase = (wid >> 2) * 64;

    const int tile = blockIdx.x;
    const int half = blockIdx.y;
    const int n    = blockIdx.z;
    int l = 0;
    while (l < 4 && tile >= c_tstart[l + 1]) l++;
    const int H = c_H[l], W = c_W[l], hw = c_hw[l], pB = c_pbase[l];
    const int base = (tile - c_tstart[l]) * 128;
    const int ch0 = half * 128;

    if (tid < 128) ((float*)smem)[tid] = cb[ch0 + tid];

    GatherCtx g;
    g.n = n; g.pB = pB; g.W = W; g.H = H; g.hw = hw;
    g.r = tid >> 1; g.su = tid & 1;
    g.flat = base + g.r;
    g.yy = (g.flat < hw) ? (g.flat / W) : 0;
    g.xx = g.flat - g.yy * W;
    g.browB = ((size_t)(ch0 + g.r)) * 2304;

    float acc[2][8][4];
#pragma unroll
    for (int i = 0; i < 2; i++)
#pragma unroll
        for (int j = 0; j < 8; j++)
#pragma unroll
            for (int k = 0; k < 4; k++) acc[i][j][k] = 0.f;

    const int rowA0 = mbase + (lane & 7) + (lane & 8);
    const int colA  = ((lane >> 4) & 1) * 16;
    const int rowB0 = nbase + (lane & 7) + ((lane >> 1) & 8);
    const int colB  = ((lane >> 3) & 1) * 16;

    prefetch_chunk(g, 0, sb + 1024);
    CP_COMMIT();

#pragma unroll 1
    for (int c = 0; c < 36; c++) {
        const int st = c & 1;
        CP_WAIT0();
        __syncthreads();
        if (c + 1 < 36) {
            prefetch_chunk(g, c + 1, sb + 1024 + (st ^ 1) * STAGE_BYTES);
            CP_COMMIT();
        }
        const uint32_t sbase = sb + 1024 + st * STAGE_BYTES;
        const uint32_t Ah = sbase, Ar = sbase + TILE_B;
        const uint32_t Bh = sbase + 2 * TILE_B, Br = sbase + 3 * TILE_B;

        // ---- window 1: hh ----
        {
            float tmp[2][8][4];
#pragma unroll
            for (int ks = 0; ks < 4; ks++) {
                uint32_t afr[2][4];
#pragma unroll
                for (int mt = 0; mt < 2; mt++) {
                    int row = rowA0 + mt * 16;
                    ldsm4(afr[mt], Ah + row * 144 + ks * 32 + colA);
                }
#pragma unroll
                for (int t = 0; t < 4; t++) {
                    uint32_t bfr[4];
                    int row = rowB0 + t * 16;
                    ldsm4(bfr, Bh + row * 144 + ks * 32 + colB);
#pragma unroll
                    for (int mt = 0; mt < 2; mt++) {
                        if (ks == 0) {
                            mma_f16_zero(tmp[mt][t * 2],     afr[mt], bfr[0], bfr[1]);
                            mma_f16_zero(tmp[mt][t * 2 + 1], afr[mt], bfr[2], bfr[3]);
                        } else {
                            mma_f16(tmp[mt][t * 2],     afr[mt], bfr[0], bfr[1]);
                            mma_f16(tmp[mt][t * 2 + 1], afr[mt], bfr[2], bfr[3]);
                        }
                    }
                }
            }
#pragma unroll
            for (int mt = 0; mt < 2; mt++)
#pragma unroll
                for (int j = 0; j < 8; j++)
#pragma unroll
                    for (int kk = 0; kk < 4; kk++)
                        acc[mt][j][kk] += tmp[mt][j][kk];
        }

        // ---- window 2: h*r' + r'*h (scaled by 2^12), one shared chain ----
        {
            float tmp[2][8][4];
#pragma unroll
            for (int ks = 0; ks < 4; ks++) {
                uint32_t ah[2][4], ar[2][4];
#pragma unroll
                for (int mt = 0; mt < 2; mt++) {
                    int row = rowA0 + mt * 16;
                    ldsm4(ah[mt], Ah + row * 144 + ks * 32 + colA);
                    ldsm4(ar[mt], Ar + row * 144 + ks * 32 + colA);
                }
#pragma unroll
                for (int t = 0; t < 4; t++) {
                    uint32_t bh[4], br[4];
                    int row = rowB0 + t * 16;
                    ldsm4(bh, Bh + row * 144 + ks * 32 + colB);
                    ldsm4(br, Br + row * 144 + ks * 32 + colB);
#pragma unroll
                    for (int mt = 0; mt < 2; mt++) {
                        if (ks == 0) {
                            mma_f16_zero(tmp[mt][t * 2],     ah[mt], br[0], br[1]);
                            mma_f16_zero(tmp[mt][t * 2 + 1], ah[mt], br[2], br[3]);
                        } else {
                            mma_f16(tmp[mt][t * 2],     ah[mt], br[0], br[1]);
                            mma_f16(tmp[mt][t * 2 + 1], ah[mt], br[2], br[3]);
                        }
                        mma_f16(tmp[mt][t * 2],     ar[mt], bh[0], bh[1]);
                        mma_f16(tmp[mt][t * 2 + 1], ar[mt], bh[2], bh[3]);
                    }
                }
            }
#pragma unroll
            for (int mt = 0; mt < 2; mt++)
#pragma unroll
                for (int j = 0; j < 8; j++)
#pragma unroll
                    for (int kk = 0; kk < 4; kk++)
                        acc[mt][j][kk] = fmaf(tmp[mt][j][kk], RINV, acc[mt][j][kk]);
        }
    }

    // epilogue: bias + relu, write g_t[pos][c]
    const float* bias = (const float*)smem;
#pragma unroll
    for (int mt = 0; mt < 2; mt++) {
#pragma unroll
        for (int nt = 0; nt < 8; nt++) {
            int nn = nbase + nt * 8 + (lane & 3) * 2;
            float bn0 = bias[nn], bn1 = bias[nn + 1];
#pragma unroll
            for (int h2 = 0; h2 < 2; h2++) {
                int m = mbase + mt * 16 + (lane >> 2) + h2 * 8;
                int fl = base + m;
                if (fl < hw) {
                    float v0 = fmaxf(acc[mt][nt][h2 * 2 + 0] + bn0, 0.f);
                    float v1 = fmaxf(acc[mt][nt][h2 * 2 + 1] + bn1, 0.f);
                    *(float2*)&g_t[((size_t)(n * MPOS + pB + fl)) * 256 + ch0 + nn] =
                        make_float2(v0, v1);
                }
            }
        }
    }
}

// ---------------------------------------------------------------------------
// 2) 1x1 heads — 2 threads per position (halved dependent-load chains)
// ---------------------------------------------------------------------------
__global__ __launch_bounds__(256)
void head1x1_kernel(const float* __restrict__ ow, const float* __restrict__ ob,
                    const float* __restrict__ dw, const float* __restrict__ db) {
    __shared__ float w2[15 * 256];
    __shared__ float b2[15];
    const int t = threadIdx.x;
    for (int i = t; i < 3 * 256; i += 256) w2[i] = ow[i];
    for (int i = t; i < 12 * 256; i += 256) w2[768 + i] = dw[i];
    if (t < 3) b2[t] = ob[t];
    else if (t < 15) b2[t] = db[t - 3];
    __syncthreads();

    const int tile = blockIdx.x;
    const int n    = blockIdx.y;
    int l = 0;
    while (l < 4 && tile >= c_tstart[l + 1]) l++;
    const int hw = c_hw[l], pB = c_pbase[l], aB = c_abase[l];
    const int t2 = t >> 1, par = t & 1;
    const int pos = (tile - c_tstart[l]) * 128 + t2;
    const bool live = (pos < hw);

    const float4* trow = (const float4*)(g_t
        + ((size_t)(n * MPOS + pB + (live ? pos : 0))) * 256 + par * 128);

    float acc[15];
#pragma unroll
    for (int o = 0; o < 15; o++) acc[o] = 0.f;

    if (live) {
#pragma unroll 4
        for (int c4 = 0; c4 < 32; c4++) {
            float4 tv = trow[c4];
#pragma unroll
            for (int o = 0; o < 15; o++) {
                const float* wr = &w2[o * 256 + par * 128 + c4 * 4];
                acc[o] += tv.x * wr[0] + tv.y * wr[1] + tv.z * wr[2] + tv.w * wr[3];
            }
        }
    }
    // combine halves (pairs are lane-adjacent; all lanes participate)
#pragma unroll
    for (int o = 0; o < 15; o++)
        acc[o] += __shfl_xor_sync(0xffffffffu, acc[o], 1);

    if (live && par == 0) {
        size_t ob_ = (size_t)n * MALL;
        int m = aB + pos * 3;
#pragma unroll
        for (int a = 0; a < 3; a++) {
            g_logits[ob_ + m + a] = acc[a] + b2[a];
#pragma unroll
            for (int d = 0; d < 4; d++)
                g_deltas[(ob_ + m + a) * 4 + d] = acc[3 + a * 4 + d] + b2[3 + a * 4 + d];
        }
    }
}

// ---------------------------------------------------------------------------
// 3) exact top-k: histogram + candidate compaction + smem bitonic sort
// ---------------------------------------------------------------------------
__device__ __forceinline__ unsigned flipf(float f) {
    unsigned u = __float_as_uint(f);
    return (u & 0x80000000u) ? ~u : (u | 0x80000000u);
}

__global__ __launch_bounds__(512)
void topk_kernel() {
    extern __shared__ unsigned long long cand[];
    __shared__ unsigned hist[2048];
    __shared__ unsigned sB1;
    __shared__ int sCnt;

    const int blk = blockIdx.x;
    const int n = blk / 5, l = blk % 5;
    const int NE = c_hwa[l];
    const int K  = c_k[l];
    const float* sc = g_logits + (size_t)n * MALL + c_abase[l];
    const int t = threadIdx.x;

    for (int i = t; i < 2048; i += 512) hist[i] = 0;
    __syncthreads();
    for (int i = t; i < NE; i += 512) atomicAdd(&hist[flipf(sc[i]) >> 21], 1u);
    __syncthreads();
    if (t == 0) {
        unsigned acc = 0; int b = 2047;
        for (; b >= 0; b--) { unsigned h = hist[b]; if (acc + h >= (unsigned)K) break; acc += h; }
        sB1 = (unsigned)b;
        sCnt = 0;
    }
    __syncthreads();
    const unsigned B1 = sB1;

    for (int i = t; i < NE; i += 512) {
        unsigned k = flipf(sc[i]);
        if ((k >> 21) >= B1) {
            int s = atomicAdd(&sCnt, 1);
            if (s < CAND)
                cand[s] = ((unsigned long long)k << 32) | (unsigned)(~(unsigned)i);
        }
    }
    __syncthreads();
    int C = sCnt < CAND ? sCnt : CAND;
    int nsort = 1024;
    while (nsort < C) nsort <<= 1;
    for (int i = C + t; i < nsort; i += 512) cand[i] = 0ull;
    __syncthreads();

    for (unsigned k2 = 2; k2 <= (unsigned)nsort; k2 <<= 1) {
        for (unsigned j = k2 >> 1; j > 0; j >>= 1) {
            __syncthreads();
            for (unsigned i = t; i < (unsigned)nsort; i += 512) {
                unsigned ixj = i ^ j;
                if (ixj > i) {
                    bool dir = ((i & k2) == 0);
                    unsigned long long a = cand[i], b = cand[ixj];
                    if ((a < b) == dir) { cand[i] = b; cand[ixj] = a; }
                }
            }
        }
    }
    __syncthreads();
    for (int s = t; s < K; s += 512)
        g_topk[blk][s] = (int)(~(unsigned)(cand[s] & 0xFFFFFFFFull));
}

// ---------------------------------------------------------------------------
// 4) decode
// ---------------------------------------------------------------------------
__global__ void decode_kernel() {
    int sid = blockIdx.x * 256 + threadIdx.x;
    if (sid >= NIMG * MPROP) return;
    int n = sid / MPROP, s = sid - n * MPROP;
    int l = s / 1000; if (l > 4) l = 4;
    int kl = s - c_sbase[l];
    int blk = n * 5 + l;
    int idx = g_topk[blk][kl];

    float score = g_logits[(size_t)n * MALL + c_abase[l] + idx];
    int pos = idx / 3, a = idx - pos * 3;
    int W = c_W[l];
    int yy = pos / W, xx = pos - yy * W;

    double size = (double)c_size[l];
    double ratio = (a == 0) ? 0.5 : ((a == 1) ? 1.0 : 2.0);
    double wd = sqrt(size * size / ratio);
    double hd = wd * ratio;

    float sx = (float)(xx * c_stride[l]);
    float sy = (float)(yy * c_stride[l]);
    float ax1 = sx + (float)(-wd * 0.5), ay1 = sy + (float)(-hd * 0.5);
    float ax2 = sx + (float)(wd * 0.5),  ay2 = sy + (float)(hd * 0.5);

    float w = ax2 - ax1, h = ay2 - ay1;
    float cx = ax1 + 0.5f * w, cy = ay1 + 0.5f * h;

    const float* dp = &g_deltas[((size_t)n * MALL + c_abase[l] + idx) * 4];
    const float CLAMP = (float)4.135166556742356;
    float dwv = fminf(dp[2], CLAMP);
    float dhv = fminf(dp[3], CLAMP);

    float pcx = dp[0] * w + cx, pcy = dp[1] * h + cy;
    float pw = expf(dwv) * w, ph = expf(dhv) * h;

    float x1 = pcx - 0.5f * pw, y1 = pcy - 0.5f * ph;
    float x2 = pcx + 0.5f * pw, y2 = pcy + 0.5f * ph;
    x1 = fminf(fmaxf(x1, 0.f), 1216.f);
    x2 = fminf(fmaxf(x2, 0.f), 1216.f);
    y1 = fminf(fmaxf(y1, 0.f), 800.f);
    y2 = fminf(fmaxf(y2, 0.f), 800.f);

    bool valid = ((x2 - x1) > 0.f) && ((y2 - y1) > 0.f);
    g_pbox[n][s] = make_float4(x1, y1, x2, y2);
    g_pscore[n][s] = valid ? score : NEG_INF;
}

// ---------------------------------------------------------------------------
// 5a-i) fill sorted arrays with deterministic padding
// ---------------------------------------------------------------------------
__global__ void fill_kernel() {
    int i = blockIdx.x * 256 + threadIdx.x;
    if (i >= NIMG * MPROP) return;
    int n = i / MPROP, s = i - n * MPROP;
    g_sbox[n][s] = make_float4(0.f, 0.f, 0.f, 0.f);
    g_sscore[n][s] = NEG_INF;
}

// ---------------------------------------------------------------------------
// 5a-ii) stable compaction of valid proposals per (image, level)
// ---------------------------------------------------------------------------
__global__ __launch_bounds__(1024)
void compact_kernel() {
    __shared__ int pref[1024];
    const int blk = blockIdx.x, n = blk / 5, l = blk % 5;
    const int K = c_k[l], sb = c_sbase[l];
    const int t = threadIdx.x;
    int flag = 0; float sc = NEG_INF; int pooled = 0;
    if (t < K) {
        pooled = sb + t;
        sc = g_pscore[n][pooled];
        flag = (sc > -5e8f) ? 1 : 0;
    }
    pref[t] = flag;
    __syncthreads();
    for (int off = 1; off < 1024; off <<= 1) {
        int v = (t >= off) ? pref[t - off] : 0;
        __syncthreads();
        pref[t] += v;
        __syncthreads();
    }
    if (flag) {
        int p = pref[t] - 1;
        g_vkey[n][l][p] = ((unsigned long long)flipf(sc) << 32) | (unsigned)(~(unsigned)pooled);
        g_vpool[n][l][p] = pooled;
    }
    if (t == 1023) g_vcnt[n][l] = pref[1023];
}

// ---------------------------------------------------------------------------
// 5a-iii) 5-way merge by rank: each valid element binary-searches other lists
// ---------------------------------------------------------------------------
__global__ __launch_bounds__(1024)
void merge_kernel() {
    const int blk = blockIdx.x, n = blk / 5, l = blk % 5;
    const int t = threadIdx.x;
    const int cnt = g_vcnt[n][l];
    if (t >= cnt) return;
    const unsigned long long K = g_vkey[n][l][t];
    int grank = t;
#pragma unroll
    for (int l2 = 0; l2 < 5; l2++) {
        if (l2 == l) continue;
        int c2 = g_vcnt[n][l2];
        const unsigned long long* lst = g_vkey[n][l2];
        int lo = 0, hi = c2;
        while (lo < hi) {
            int mid = (lo + hi) >> 1;
            if (lst[mid] > K) lo = mid + 1; else hi = mid;
        }
        grank += lo;
    }
    int pooled = g_vpool[n][l][t];
    g_sbox[n][grank]   = g_pbox[n][pooled];
    g_sscore[n][grank] = g_pscore[n][pooled];
}

// ---------------------------------------------------------------------------
// 5b) suppression bitmask (row padded to NWP words)
// ---------------------------------------------------------------------------
__global__ __launch_bounds__(512)
void mask_kernel() {
    __shared__ float4 jb[128];
    const int n = blockIdx.z;
    const int tid = threadIdx.x;
    const int i = blockIdx.x * 128 + (tid & 127);
    const int wloc = tid >> 7;
    const int w = blockIdx.y * 4 + wloc;
    const int j0 = blockIdx.y * 128;

    if (tid < 128) {
        int j = j0 + tid;
        jb[tid] = (j < MPROP) ? g_sbox[n][j] : make_float4(0.f, 0.f, 0.f, 0.f);
    }
    __syncthreads();
    if (i >= MPROP || w >= NWP) return;

    float4 b = g_sbox[n][i];
    float a1 = (b.z - b.x) * (b.w - b.y);
    unsigned bits = 0u;
#pragma unroll
    for (int jj = 0; jj < 32; jj++) {
        int j = w * 32 + jj;
        if (j < MPROP) {
            float4 c = jb[wloc * 32 + jj];
            float lx = fmaxf(b.x, c.x), ly = fmaxf(b.y, c.y);
            float rx = fminf(b.z, c.z), ry = fminf(b.w, c.w);
            float iw = fmaxf(rx - lx, 0.f), ih = fmaxf(ry - ly, 0.f);
            float inter = iw * ih;
            float a2 = (c.z - c.x) * (c.w - c.y);
            float iou = inter / fmaxf(a1 + a2 - inter, 1e-9f);
            if (iou > 0.7f) bits |= (1u << jj);
        }
    }
    g_mask[n][i][w] = bits;
}

// ---------------------------------------------------------------------------
// 5c) chunked scan: 32 candidates per chunk, double-buffered mask rows
// ---------------------------------------------------------------------------
#define CMBYTES (2 * 32 * NWP * 4)
#define SCAN_SMEM (CMBYTES + MPROP * 4)

__global__ __launch_bounds__(256)
void scan_kernel(float* __restrict__ out) {
    extern __shared__ char sm[];
    unsigned* cm  = (unsigned*)sm;
    float*    ssc = (float*)(sm + CMBYTES);
    __shared__ unsigned removed[NWP];
    __shared__ int selj[32];
    __shared__ int s_cnt;
    __shared__ unsigned s_selbits;
    __shared__ int s_vcnt;

    const int n = blockIdx.x;
    const int t = threadIdx.x;
    const uint32_t cm_s = smem_u32(cm);

    for (int i = t; i < MPROP; i += 256) ssc[i] = g_sscore[n][i];
    for (int w = t; w < NWP; w += 256) removed[w] = 0u;
    if (t == 0) s_vcnt = 0;
    __syncthreads();
    {
        int cnt = 0;
        for (int i = t; i < MPROP; i += 256)
            if (ssc[i] > -5e8f) cnt++;
        if (cnt) atomicAdd(&s_vcnt, cnt);
    }
    __syncthreads();
    const int vlimit = s_vcnt;
    const int nchunks = (vlimit + 31) >> 5;

    if (nchunks > 0) {
        int rows = (32 < MPROP) ? 32 : MPROP;
        for (int idx = t; idx < rows * (NWP / 4); idx += 256) {
            int rr = idx / (NWP / 4), u = idx % (NWP / 4);
            cp_async16(cm_s + (rr * NWP + u * 4) * 4, &g_mask[n][rr][u * 4], 16u);
        }
        CP_COMMIT();
    }

    int k = 0;
    for (int c = 0; c < nchunks && k < POSTK; c++) {
        CP_WAIT0();
        __syncthreads();
        const int buf = c & 1;
        if (c + 1 < nchunks) {
            int j0n = (c + 1) * 32;
            int rows = MPROP - j0n; if (rows > 32) rows = 32;
            uint32_t db = cm_s + ((c + 1) & 1) * 32 * NWP * 4;
            for (int idx = t; idx < rows * (NWP / 4); idx += 256) {
                int rr = idx / (NWP / 4), u = idx % (NWP / 4);
                cp_async16(db + (rr * NWP + u * 4) * 4, &g_mask[n][j0n + rr][u * 4], 16u);
            }
            CP_COMMIT();
        }
        const int j0 = c * 32;
        const int nc = (vlimit - j0 < 32) ? (vlimit - j0) : 32;
        const unsigned* cmb = cm + buf * 32 * NWP;

        if (t == 0) {
            unsigned lrm = removed[c];
            unsigned selbits = 0;
            int cnt = 0;
            for (int kk = 0; kk < nc; kk++) {
                if (!((lrm >> kk) & 1u)) {
                    selbits |= 1u << kk;
                    selj[cnt++] = j0 + kk;
                    lrm |= cmb[kk * NWP + c];
                    if (k + cnt == POSTK) break;
                }
            }
            s_selbits = selbits;
            s_cnt = cnt;
        }
        __syncthreads();
        const unsigned selbits = s_selbits;
        const int cnt = s_cnt;
        if (selbits) {
            for (int w = t; w < NWP; w += 256) {
                unsigned orv = removed[w];
                unsigned sb2 = selbits;
                while (sb2) {
                    int kk = __ffs(sb2) - 1;
                    sb2 &= sb2 - 1;
                    orv |= cmb[kk * NWP + w];
                }
                removed[w] = orv;
            }
            if (t < cnt) {
                int j = selj[t];
                float4 b = g_sbox[n][j];
                float* o = out + ((size_t)n * POSTK + k + t) * 5;
                o[0] = b.x; o[1] = b.y; o[2] = b.z; o[3] = b.w; o[4] = ssc[j];
            }
        }
        k += cnt;
        __syncthreads();
    }
    for (int r = k + t; r < POSTK; r += 256) {
        float* o = out + ((size_t)n * POSTK + r) * 5;
        o[0] = 0.f; o[1] = 0.f; o[2] = 0.f; o[3] = 0.f; o[4] = NEG_INF;
    }
}

// ---------------------------------------------------------------------------
// launch
// ---------------------------------------------------------------------------
extern "C" void kernel_launch(void* const* d_in, const int* in_sizes, int n_in,
                              void* d_out, int out_size) {
    const float* feats[5];
    for (int i = 0; i < 5; i++) feats[i] = (const float*)d_in[i];
    const float* conv_w  = (const float*)d_in[5];
    const float* conv_b  = (const float*)d_in[6];
    const float* obj_w   = (const float*)d_in[7];
    const float* obj_b   = (const float*)d_in[8];
    const float* delta_w = (const float*)d_in[9];
    const float* delta_b = (const float*)d_in[10];
    float* out = (float*)d_out;

    cudaFuncSetAttribute(conv_mma_kernel, cudaFuncAttributeMaxDynamicSharedMemorySize, CMMA_SMEM);
    cudaFuncSetAttribute(topk_kernel, cudaFuncAttributeMaxDynamicSharedMemorySize, CAND * 8);
    cudaFuncSetAttribute(scan_kernel, cudaFuncAttributeMaxDynamicSharedMemorySize, SCAN_SMEM);

    split_w_kernel<<<256, 256>>>(conv_w);
    {
        dim3 grid(1267, 4, NIMG);
        split_feat_kernel<<<grid, 256>>>(feats[0], feats[1], feats[2], feats[3], feats[4]);
    }
    {
        dim3 grid(634, 2, NIMG);
        conv_mma_kernel<<<grid, 256, CMMA_SMEM>>>(conv_b);
    }
    {
        dim3 grid(634, NIMG);
        head1x1_kernel<<<grid, 256>>>(obj_w, obj_b, delta_w, delta_b);
    }
    topk_kernel<<<10, 512, CAND * 8>>>();
    decode_kernel<<<(NIMG * MPROP + 255) / 256, 256>>>();

    fill_kernel<<<(NIMG * MPROP + 255) / 256, 256>>>();
    compact_kernel<<<10, 1024>>>();
    merge_kernel<<<10, 1024>>>();
    {
        dim3 grid((MPROP + 127) / 128, (NWP + 3) / 4, NIMG);
        mask_kernel<<<grid, 512>>>();
    }
    scan_kernel<<<NIMG, 256, SCAN_SMEM>>>(out);
}